// round 11
// baseline (speedup 1.0000x reference)
#include <cuda_runtime.h>
#include <cuda_fp16.h>
#include <math.h>
#include <stdint.h>

#define NN 10000
#define E0 80000
#define EE 90000
#define F0 512
#define F1 4096
#define F2 1024
#define F3 7
#define NSLOPE 0.2f

// ---------------- scratch (static device globals; no allocation) ----------------
__device__ __half g_agg1h[(size_t)NN * F0];     // half agg (A of GEMM1)
__device__ __half g_h1h[(size_t)NN * F1];       // half h1 (A of GEMM2)
__device__ float  g_h2[(size_t)NN * F2];
__device__ float  g_agg2[(size_t)NN * F2];
__device__ float  g_h3[NN * F3];
__device__ float  g_ssrc[NN], g_sdst[NN];
__device__ float  g_v1s[F0], g_v1d[F0];
__device__ __half g_w1t[(size_t)F1 * F0];       // W1^T half [N][K]
__device__ __half g_w2t[(size_t)F2 * F1];       // W2^T half [N][K]
__device__ float  g_ew[EE];                     // per-edge alpha (per layer)
// CSR by destination
__device__ int g_deg[NN];
__device__ int g_cursor[NN];
__device__ int g_off[NN + 1];
__device__ int g_csr[EE];

__device__ __forceinline__ void edge_sd(const int* __restrict__ ei, int e, int& s, int& d) {
    if (e < E0) { s = ei[e]; d = ei[E0 + e]; }
    else        { s = e - E0; d = e - E0; }
}
__device__ __forceinline__ uint32_t smem_u32(const void* p) {
    uint32_t a;
    asm("{ .reg .u64 t; cvta.to.shared.u64 t, %1; cvt.u32.u64 %0, t; }" : "=r"(a) : "l"(p));
    return a;
}
__device__ __forceinline__ void cpa16(uint32_t dst, const void* src, int sz) {
    asm volatile("cp.async.cg.shared.global [%0], [%1], 16, %2;"
                 :: "r"(dst), "l"(src), "r"(sz));
}
__device__ __forceinline__ void mma16(float* c, const uint32_t* a, const uint32_t* b) {
    asm volatile(
        "mma.sync.aligned.m16n8k16.row.col.f32.f16.f16.f32 "
        "{%0,%1,%2,%3}, {%4,%5,%6,%7}, {%8,%9}, {%0,%1,%2,%3};"
        : "+f"(c[0]), "+f"(c[1]), "+f"(c[2]), "+f"(c[3])
        : "r"(a[0]), "r"(a[1]), "r"(a[2]), "r"(a[3]), "r"(b[0]), "r"(b[1]));
}
__device__ __forceinline__ void ldm4(uint32_t* r, uint32_t addr) {
    asm volatile("ldmatrix.sync.aligned.m8n8.x4.shared.b16 {%0,%1,%2,%3}, [%4];"
                 : "=r"(r[0]), "=r"(r[1]), "=r"(r[2]), "=r"(r[3]) : "r"(addr));
}
__device__ __forceinline__ float lrelu(float v) { return (v > 0.f) ? v : NSLOPE * v; }

// ---------------- weight transpose + fp16 convert: out[n][k] = half(in[k][n]) ----------------
__global__ void k_transpose_h(const float* __restrict__ in, __half* __restrict__ out,
                              int K, int N) {
    __shared__ __half tile[32][34];
    int n0 = blockIdx.x * 32, k0 = blockIdx.y * 32;
    int tx = threadIdx.x, ty = threadIdx.y;   // 32 x 8
    #pragma unroll
    for (int i = 0; i < 4; i++) {
        int k = k0 + ty + i * 8;
        tile[ty + i * 8][tx] = __float2half_rn(in[(size_t)k * N + n0 + tx]);
    }
    __syncthreads();
    #pragma unroll
    for (int i = 0; i < 4; i++) {
        int n = n0 + ty + i * 8;
        out[(size_t)n * K + k0 + tx] = tile[tx][ty + i * 8];
    }
}

// ---------------- CSR build ----------------
__global__ void k_zerodeg() {
    int i = blockIdx.x * blockDim.x + threadIdx.x;
    if (i < NN) g_deg[i] = 0;
}
__global__ void k_deg(const int* __restrict__ ei) {
    int e = blockIdx.x * blockDim.x + threadIdx.x;
    if (e >= EE) return;
    int s, d; edge_sd(ei, e, s, d);
    atomicAdd(&g_deg[d], 1);
}
__global__ void k_scan() {   // single block, 1024 threads, chunk=10
    __shared__ int sh[1024];
    int tid = threadIdx.x;
    int base = tid * 10;
    int cnt[10]; int local = 0;
    #pragma unroll
    for (int i = 0; i < 10; i++) {
        int idx = base + i;
        int c = (idx < NN) ? g_deg[idx] : 0;
        cnt[i] = local; local += c;
    }
    sh[tid] = local;
    __syncthreads();
    for (int off = 1; off < 1024; off <<= 1) {
        int v = (tid >= off) ? sh[tid - off] : 0;
        __syncthreads();
        sh[tid] += v;
        __syncthreads();
    }
    int start = sh[tid] - local;
    #pragma unroll
    for (int i = 0; i < 10; i++) {
        int idx = base + i;
        if (idx < NN) { g_off[idx] = start + cnt[i]; g_cursor[idx] = 0; }
    }
    if (tid == 1023) g_off[NN] = sh[1023];
}
__global__ void k_fill(const int* __restrict__ ei) {
    int e = blockIdx.x * blockDim.x + threadIdx.x;
    if (e >= EE) return;
    int s, d; edge_sd(ei, e, s, d);
    int p = atomicAdd(&g_cursor[d], 1);
    g_csr[g_off[d] + p] = s;
}

// ---------------- attention-vector & node-score kernels ----------------
__global__ void k_v1(const float* __restrict__ W1, const float* __restrict__ as,
                     const float* __restrict__ ad) {
    int r = blockIdx.x;
    int tid = threadIdx.x;
    float ss = 0.f, sd = 0.f;
    const float* wrow = W1 + (size_t)r * F1;
    for (int j = tid; j < F1; j += 256) {
        float w = wrow[j];
        ss += w * as[j];
        sd += w * ad[j];
    }
    __shared__ float s1[256], s2[256];
    s1[tid] = ss; s2[tid] = sd;
    __syncthreads();
    for (int s = 128; s > 0; s >>= 1) {
        if (tid < s) { s1[tid] += s1[tid + s]; s2[tid] += s2[tid + s]; }
        __syncthreads();
    }
    if (tid == 0) { g_v1s[r] = s1[0]; g_v1d[r] = s2[0]; }
}

__global__ void k_scores(const float* __restrict__ X, const float* __restrict__ vs,
                         const float* __restrict__ vd, int F) {
    int node = blockIdx.x;
    int tid = threadIdx.x;      // 128
    const float* xr = X + (size_t)node * F;
    float ss = 0.f, sd = 0.f;
    for (int j = tid; j < F; j += 128) {
        float x = xr[j];
        ss += x * vs[j];
        sd += x * vd[j];
    }
    __shared__ float s1[128], s2[128];
    s1[tid] = ss; s2[tid] = sd;
    __syncthreads();
    for (int s = 64; s > 0; s >>= 1) {
        if (tid < s) { s1[tid] += s1[tid + s]; s2[tid] += s2[tid + s]; }
        __syncthreads();
    }
    if (tid == 0) { g_ssrc[node] = s1[0]; g_sdst[node] = s2[0]; }
}

// ---------------- per-node softmax -> per-edge alpha (warp per node) ----------------
__global__ void k_nd() {
    int w = (blockIdx.x * blockDim.x + threadIdx.x) >> 5;
    if (w >= NN) return;
    int lane = threadIdx.x & 31;
    int rs = g_off[w], re = g_off[w + 1];
    float sdv = g_sdst[w];
    float m = -1e30f;
    for (int j = rs + lane; j < re; j += 32)
        m = fmaxf(m, lrelu(g_ssrc[g_csr[j]] + sdv));
    #pragma unroll
    for (int o = 16; o > 0; o >>= 1) m = fmaxf(m, __shfl_xor_sync(0xffffffff, m, o));
    float den = 0.f;
    for (int j = rs + lane; j < re; j += 32)
        den += __expf(lrelu(g_ssrc[g_csr[j]] + sdv) - m);
    #pragma unroll
    for (int o = 16; o > 0; o >>= 1) den += __shfl_xor_sync(0xffffffff, den, o);
    float inv = 1.0f / den;
    for (int j = rs + lane; j < re; j += 32)
        g_ew[j] = __expf(lrelu(g_ssrc[g_csr[j]] + sdv) - m) * inv;
}

// ---------------- gather aggregation (weights precomputed, no atomics) ----------------
__global__ void k_gat1(const float* __restrict__ x) {
    int n = blockIdx.x, tid = threadIdx.x;   // 128 threads
    int rs = g_off[n], re = g_off[n + 1];
    float4 acc = make_float4(0.f, 0.f, 0.f, 0.f);
    int j = rs;
    for (; j + 2 <= re; j += 2) {
        int s0 = g_csr[j], s1 = g_csr[j + 1];
        float w0 = g_ew[j], w1 = g_ew[j + 1];
        float4 v0 = ((const float4*)(x + (size_t)s0 * F0))[tid];
        float4 v1 = ((const float4*)(x + (size_t)s1 * F0))[tid];
        acc.x += w0 * v0.x; acc.y += w0 * v0.y; acc.z += w0 * v0.z; acc.w += w0 * v0.w;
        acc.x += w1 * v1.x; acc.y += w1 * v1.y; acc.z += w1 * v1.z; acc.w += w1 * v1.w;
    }
    if (j < re) {
        int s0 = g_csr[j];
        float w0 = g_ew[j];
        float4 v0 = ((const float4*)(x + (size_t)s0 * F0))[tid];
        acc.x += w0 * v0.x; acc.y += w0 * v0.y; acc.z += w0 * v0.z; acc.w += w0 * v0.w;
    }
    __half2 h0 = __floats2half2_rn(acc.x, acc.y);
    __half2 h1v = __floats2half2_rn(acc.z, acc.w);
    __half2* o = (__half2*)(g_agg1h + (size_t)n * F0);
    o[tid * 2 + 0] = h0;
    o[tid * 2 + 1] = h1v;
}

__global__ void k_gat2(const float* __restrict__ b2) {
    int n = blockIdx.x, tid = threadIdx.x;   // 256 threads
    int rs = g_off[n], re = g_off[n + 1];
    float4 acc = make_float4(0.f, 0.f, 0.f, 0.f);
    int j = rs;
    for (; j + 2 <= re; j += 2) {
        int s0 = g_csr[j], s1 = g_csr[j + 1];
        float w0 = g_ew[j], w1 = g_ew[j + 1];
        float4 v0 = ((const float4*)(g_h2 + (size_t)s0 * F2))[tid];
        float4 v1 = ((const float4*)(g_h2 + (size_t)s1 * F2))[tid];
        acc.x += w0 * v0.x; acc.y += w0 * v0.y; acc.z += w0 * v0.z; acc.w += w0 * v0.w;
        acc.x += w1 * v1.x; acc.y += w1 * v1.y; acc.z += w1 * v1.z; acc.w += w1 * v1.w;
    }
    if (j < re) {
        int s0 = g_csr[j];
        float w0 = g_ew[j];
        float4 v0 = ((const float4*)(g_h2 + (size_t)s0 * F2))[tid];
        acc.x += w0 * v0.x; acc.y += w0 * v0.y; acc.z += w0 * v0.z; acc.w += w0 * v0.w;
    }
    float4 bv = ((const float4*)b2)[tid];
    acc.x = fmaxf(acc.x + bv.x, 0.f);
    acc.y = fmaxf(acc.y + bv.y, 0.f);
    acc.z = fmaxf(acc.z + bv.z, 0.f);
    acc.w = fmaxf(acc.w + bv.w, 0.f);
    ((float4*)(g_agg2 + (size_t)n * F2))[tid] = acc;
}

// ---------------- layer 3: warp-per-node GEMM (agg2 read once) ----------------
__global__ void k_gemm3(const float* __restrict__ W3) {
    int w = (blockIdx.x * blockDim.x + threadIdx.x) >> 5;
    if (w >= NN) return;
    int lane = threadIdx.x & 31;
    const float* a = g_agg2 + (size_t)w * F2;
    float acc[F3];
    #pragma unroll
    for (int j = 0; j < F3; j++) acc[j] = 0.f;
    for (int k = lane; k < F2; k += 32) {
        float av = a[k];
        #pragma unroll
        for (int j = 0; j < F3; j++) acc[j] += av * W3[k * F3 + j];
    }
    #pragma unroll
    for (int j = 0; j < F3; j++) {
        float s = acc[j];
        #pragma unroll
        for (int o = 16; o > 0; o >>= 1) s += __shfl_xor_sync(0xffffffff, s, o);
        if (lane == 0) g_h3[w * F3 + j] = s;
    }
}

__global__ void k_gat3f(const float* __restrict__ b3, float* __restrict__ out) {
    int wg = (blockIdx.x * blockDim.x + threadIdx.x) >> 5;
    if (wg >= NN) return;
    int lane = threadIdx.x & 31;
    int rs = g_off[wg], re = g_off[wg + 1];
    float acc = 0.f;
    for (int j = rs; j < re; j++) {
        int s = g_csr[j];
        float w = g_ew[j];
        if (lane < F3) acc += w * g_h3[s * F3 + lane];
    }
    float z = (lane < F3) ? acc + b3[lane] : -1e30f;
    float mz = z;
    #pragma unroll
    for (int o = 16; o > 0; o >>= 1) mz = fmaxf(mz, __shfl_xor_sync(0xffffffff, mz, o));
    float e = (lane < F3) ? expf(z - mz) : 0.f;
    #pragma unroll
    for (int o = 16; o > 0; o >>= 1) e += __shfl_xor_sync(0xffffffff, e, o);
    float l = mz + logf(e);
    if (lane < F3) out[wg * F3 + lane] = z - l;
}

// ---------------- fp16 mma.sync GEMM, ldmatrix + 3-stage cp.async ----------------
// Template WM = warps along M. BM = WM*32, BN = 256, BK = 64, 512 threads.
// WM=4: warp tile 32x64 (NU=8). WM=2: warp tile 32x32 (NU=4), for wave quantization.
#define SH_STR 72
#define NSTAGE 3
#define STB_B (256 * SH_STR * 2)                 // 36864 bytes (B tile, fixed)

template<int WM>
__global__ void __launch_bounds__(512, 1)
tc_gemm(const __half* __restrict__ A, const __half* __restrict__ Bt, void* __restrict__ Cv,
        int M, int Nc, int K, const float* __restrict__ bias, int doRelu, int outHalf) {
    constexpr int BM  = WM * 32;
    constexpr int NWN = 16 / WM;
    constexpr int WNC = 256 / NWN;               // cols per warp
    constexpr int NU  = WNC / 8;                 // n8 tiles per warp
    constexpr int STA = BM * SH_STR * 2;         // A tile bytes
    constexpr int STBY = STA + STB_B;            // stage bytes
    constexpr int AIT = (BM * 8) / 512;          // A fill iters

    extern __shared__ __half smh[];
    uint32_t smu = smem_u32(smh);
    int tid = threadIdx.x;
    int lane = tid & 31, wid = tid >> 5;
    int warp_m = wid % WM, warp_n = wid / WM;
    int g = lane >> 2, c = lane & 3;
    int lr = lane & 7, lm = lane >> 3;
    int row0 = blockIdx.y * BM, col0 = blockIdx.x * 256;

    uint32_t a_loff = ((uint32_t)(warp_m * 32 + lr + (lm & 1) * 8) * SH_STR
                       + ((lm >> 1) & 1) * 8) * 2;
    uint32_t b_loff = (uint32_t)STA
                      + ((uint32_t)(warp_n * WNC + lr + ((lm >> 1) & 1) * 8) * SH_STR
                         + (lm & 1) * 8) * 2;

    float acc[2][NU][4];
    #pragma unroll
    for (int t = 0; t < 2; t++)
        #pragma unroll
        for (int u = 0; u < NU; u++)
            #pragma unroll
            for (int j = 0; j < 4; j++) acc[t][u][j] = 0.f;

    const int KT = K >> 6;

    auto fill = [&](int kt, int stage) {
        uint32_t sa_u = smu + stage * STBY;
        uint32_t sb_u = sa_u + STA;
        #pragma unroll
        for (int i = 0; i < AIT; i++) {
            int idx = i * 512 + tid;
            int m = idx >> 3, k8 = idx & 7;
            int gr = row0 + m;
            int ok = gr < M;
            const __half* src = A + (size_t)(ok ? gr : row0) * K + kt * 64 + k8 * 8;
            cpa16(sa_u + (uint32_t)(m * SH_STR + k8 * 8) * 2, src, ok ? 16 : 0);
        }
        #pragma unroll
        for (int i = 0; i < 4; i++) {
            int idx = i * 512 + tid;
            int n = idx >> 3, k8 = idx & 7;
            const __half* src = Bt + (size_t)(col0 + n) * K + kt * 64 + k8 * 8;
            cpa16(sb_u + (uint32_t)(n * SH_STR + k8 * 8) * 2, src, 16);
        }
        asm volatile("cp.async.commit_group;" ::: "memory");
    };

    fill(0, 0);
    if (KT > 1) fill(1, 1);

    for (int kt = 0; kt < KT; kt++) {
        int buf = kt % NSTAGE;
        if (kt + 2 < KT) {
            fill(kt + 2, (kt + 2) % NSTAGE);
            asm volatile("cp.async.wait_group 2;" ::: "memory");
        } else if (kt + 1 < KT) {
            asm volatile("cp.async.wait_group 1;" ::: "memory");
        } else {
            asm volatile("cp.async.wait_group 0;" ::: "memory");
        }
        __syncthreads();
        uint32_t st = smu + buf * STBY;
        #pragma unroll
        for (int ks = 0; ks < 4; ks++) {
            uint32_t af[2][4];
            #pragma unroll
            for (int t = 0; t < 2; t++)
                ldm4(af[t], st + a_loff + (uint32_t)(t * 16 * SH_STR * 2) + ks * 32);
            uint32_t bf[NU][2];
            #pragma unroll
            for (int p = 0; p < NU / 2; p++) {
                uint32_t r4[4];
                ldm4(r4, st + b_loff + (uint32_t)(p * 16 * SH_STR * 2) + ks * 32);
                bf[p * 2][0] = r4[0];     bf[p * 2][1] = r4[1];
                bf[p * 2 + 1][0] = r4[2]; bf[p * 2 + 1][1] = r4[3];
            }
            #pragma unroll
            for (int t = 0; t < 2; t++)
                #pragma unroll
                for (int u = 0; u < NU; u++)
                    mma16(acc[t][u], af[t], bf[u]);
        }
        __syncthreads();
    }

    // epilogue
    #pragma unroll
    for (int t = 0; t < 2; t++) {
        int r0 = row0 + warp_m * 32 + t * 16 + g;
        #pragma unroll
        for (int u = 0; u < NU; u++) {
            int cc = col0 + warp_n * WNC + u * 8 + 2 * c;
            float2 v0 = make_float2(acc[t][u][0], acc[t][u][1]);
            float2 v1 = make_float2(acc[t][u][2], acc[t][u][3]);
            if (bias) {
                float b0v = bias[cc], b1v = bias[cc + 1];
                v0.x += b0v; v0.y += b1v;
                v1.x += b0v; v1.y += b1v;
            }
            if (doRelu) {
                v0.x = fmaxf(v0.x, 0.f); v0.y = fmaxf(v0.y, 0.f);
                v1.x = fmaxf(v1.x, 0.f); v1.y = fmaxf(v1.y, 0.f);
            }
            if (outHalf) {
                __half* C = (__half*)Cv;
                if (r0 < M)
                    *(__half2*)(C + (size_t)r0 * Nc + cc) = __floats2half2_rn(v0.x, v0.y);
                if (r0 + 8 < M)
                    *(__half2*)(C + (size_t)(r0 + 8) * Nc + cc) = __floats2half2_rn(v1.x, v1.y);
            } else {
                float* C = (float*)Cv;
                if (r0 < M)     *(float2*)(C + (size_t)r0 * Nc + cc) = v0;
                if (r0 + 8 < M) *(float2*)(C + (size_t)(r0 + 8) * Nc + cc) = v1;
            }
        }
    }
}

#define SMB_WM4 (NSTAGE * (128 * SH_STR * 2 + STB_B))   // 165888
#define SMB_WM2 (NSTAGE * (64 * SH_STR * 2 + STB_B))    // 138240

// ---------------- launch ----------------
extern "C" void kernel_launch(void* const* d_in, const int* in_sizes, int n_in,
                              void* d_out, int out_size) {
    const float* x   = (const float*)d_in[0];
    const int*   ei  = (const int*)d_in[1];
    const float* W1  = (const float*)d_in[2];
    const float* as1 = (const float*)d_in[3];
    const float* ad1 = (const float*)d_in[4];
    const float* b1  = (const float*)d_in[5];
    const float* W2  = (const float*)d_in[6];
    const float* as2 = (const float*)d_in[7];
    const float* ad2 = (const float*)d_in[8];
    const float* b2  = (const float*)d_in[9];
    const float* W3  = (const float*)d_in[10];
    const float* as3 = (const float*)d_in[11];
    const float* ad3 = (const float*)d_in[12];
    const float* b3  = (const float*)d_in[13];
    float* out = (float*)d_out;

    void *p_agg1h, *p_agg2, *p_h1h, *p_h2, *p_h3, *p_v1s, *p_v1d, *p_w1t, *p_w2t;
    cudaGetSymbolAddress(&p_agg1h, g_agg1h);
    cudaGetSymbolAddress(&p_agg2, g_agg2);
    cudaGetSymbolAddress(&p_h1h, g_h1h);
    cudaGetSymbolAddress(&p_h2, g_h2);
    cudaGetSymbolAddress(&p_h3, g_h3);
    cudaGetSymbolAddress(&p_v1s, g_v1s);
    cudaGetSymbolAddress(&p_v1d, g_v1d);
    cudaGetSymbolAddress(&p_w1t, g_w1t);
    cudaGetSymbolAddress(&p_w2t, g_w2t);

    cudaFuncSetAttribute(tc_gemm<4>, cudaFuncAttributeMaxDynamicSharedMemorySize, SMB_WM4);
    cudaFuncSetAttribute(tc_gemm<2>, cudaFuncAttributeMaxDynamicSharedMemorySize, SMB_WM2);

    const int EB = (EE + 255) / 256;
    const int MB128 = (NN + 127) / 128;
    const int MB64 = (NN + 63) / 64;
    const int NWB = (NN * 32 + 255) / 256;   // warp-per-node grids

    // ---- weight transpose + fp16 convert (once, independent) ----
    k_transpose_h<<<dim3(F1 / 32, F0 / 32), dim3(32, 8)>>>(W1, (__half*)p_w1t, F0, F1);
    k_transpose_h<<<dim3(F2 / 32, F1 / 32), dim3(32, 8)>>>(W2, (__half*)p_w2t, F1, F2);

    // ---- CSR build (reused by all 3 layers) ----
    k_zerodeg<<<(NN + 255) / 256, 256>>>();
    k_deg<<<EB, 256>>>(ei);
    k_scan<<<1, 1024>>>();
    k_fill<<<EB, 256>>>(ei);

    // ---- Layer 1: scores on x, alpha, gather (->half), GEMM (WM=4) ----
    k_v1<<<F0, 256>>>(W1, as1, ad1);
    k_scores<<<NN, 128>>>(x, (const float*)p_v1s, (const float*)p_v1d, F0);
    k_nd<<<NWB, 256>>>();
    k_gat1<<<NN, 128>>>(x);
    {
        dim3 grd(F1 / 256, MB128);
        tc_gemm<4><<<grd, 512, SMB_WM4>>>((const __half*)p_agg1h, (const __half*)p_w1t,
                                          p_h1h, NN, F1, F0, b1, 1, 1);
    }

    // ---- Layer 2: GEMM (WM=2, better wave fill), scores, alpha, gather ----
    {
        dim3 grd(F2 / 256, MB64);
        tc_gemm<2><<<grd, 512, SMB_WM2>>>((const __half*)p_h1h, (const __half*)p_w2t,
                                          p_h2, NN, F2, F1, nullptr, 0, 0);
    }
    k_scores<<<NN, 128>>>((const float*)p_h2, as2, ad2, F2);
    k_nd<<<NWB, 256>>>();
    k_gat2<<<NN, 256>>>(b2);

    // ---- Layer 3: warp-per-node GEMM, scores, alpha, fused gather+log_softmax ----
    k_gemm3<<<NWB, 256>>>(W3);
    k_scores<<<NN, 128>>>((const float*)p_h3, as3, ad3, F3);
    k_nd<<<NWB, 256>>>();
    k_gat3f<<<NWB, 256>>>(b3, out);
}

// round 13
// speedup vs baseline: 1.0627x; 1.0627x over previous
#include <cuda_runtime.h>
#include <cuda_fp16.h>
#include <math.h>
#include <stdint.h>

#define NN 10000
#define E0 80000
#define EE 90000
#define F0 512
#define F1 4096
#define F2 1024
#define F3 7
#define NSLOPE 0.2f

// ---------------- scratch (static device globals; no allocation) ----------------
__device__ __half g_agg1h[(size_t)NN * F0];     // half agg (A of GEMM1)
__device__ __half g_h1h[(size_t)NN * F1];       // half h1 (A of GEMM2)
__device__ float  g_h2[(size_t)NN * F2];
__device__ float  g_agg2[(size_t)NN * F2];
__device__ float  g_h3[NN * F3];
__device__ float  g_ssrc[NN], g_sdst[NN];
__device__ float  g_v1s[F0], g_v1d[F0];
__device__ __half g_w1t[(size_t)F1 * F0];       // W1^T half [N][K]
__device__ __half g_w2t[(size_t)F2 * F1];       // W2^T half [N][K]
__device__ float  g_ew[EE];                     // per-edge alpha (per layer)
// CSR by destination
__device__ int g_deg[NN];
__device__ int g_cursor[NN];
__device__ int g_off[NN + 1];
__device__ int g_csr[EE];

__device__ __forceinline__ void edge_sd(const int* __restrict__ ei, int e, int& s, int& d) {
    if (e < E0) { s = ei[e]; d = ei[E0 + e]; }
    else        { s = e - E0; d = e - E0; }
}
__device__ __forceinline__ uint32_t smem_u32(const void* p) {
    uint32_t a;
    asm("{ .reg .u64 t; cvta.to.shared.u64 t, %1; cvt.u32.u64 %0, t; }" : "=r"(a) : "l"(p));
    return a;
}
__device__ __forceinline__ void cpa16(uint32_t dst, const void* src, int sz) {
    asm volatile("cp.async.cg.shared.global [%0], [%1], 16, %2;"
                 :: "r"(dst), "l"(src), "r"(sz));
}
__device__ __forceinline__ void mma16(float* c, const uint32_t* a, const uint32_t* b) {
    asm volatile(
        "mma.sync.aligned.m16n8k16.row.col.f32.f16.f16.f32 "
        "{%0,%1,%2,%3}, {%4,%5,%6,%7}, {%8,%9}, {%0,%1,%2,%3};"
        : "+f"(c[0]), "+f"(c[1]), "+f"(c[2]), "+f"(c[3])
        : "r"(a[0]), "r"(a[1]), "r"(a[2]), "r"(a[3]), "r"(b[0]), "r"(b[1]));
}
__device__ __forceinline__ void ldm4(uint32_t* r, uint32_t addr) {
    asm volatile("ldmatrix.sync.aligned.m8n8.x4.shared.b16 {%0,%1,%2,%3}, [%4];"
                 : "=r"(r[0]), "=r"(r[1]), "=r"(r[2]), "=r"(r[3]) : "r"(addr));
}
__device__ __forceinline__ float lrelu(float v) { return (v > 0.f) ? v : NSLOPE * v; }

// ---------------- weight transpose + fp16 convert: out[n][k] = half(in[k][n]) ----------------
__global__ void k_transpose_h(const float* __restrict__ in, __half* __restrict__ out,
                              int K, int N) {
    __shared__ __half tile[32][34];
    int n0 = blockIdx.x * 32, k0 = blockIdx.y * 32;
    int tx = threadIdx.x, ty = threadIdx.y;   // 32 x 8
    #pragma unroll
    for (int i = 0; i < 4; i++) {
        int k = k0 + ty + i * 8;
        tile[ty + i * 8][tx] = __float2half_rn(in[(size_t)k * N + n0 + tx]);
    }
    __syncthreads();
    #pragma unroll
    for (int i = 0; i < 4; i++) {
        int n = n0 + ty + i * 8;
        out[(size_t)n * K + k0 + tx] = tile[tx][ty + i * 8];
    }
}

// ---------------- CSR build ----------------
__global__ void k_zerodeg() {
    int i = blockIdx.x * blockDim.x + threadIdx.x;
    if (i < NN) g_deg[i] = 0;
}
__global__ void k_deg(const int* __restrict__ ei) {
    int e = blockIdx.x * blockDim.x + threadIdx.x;
    if (e >= EE) return;
    int s, d; edge_sd(ei, e, s, d);
    atomicAdd(&g_deg[d], 1);
}
__global__ void k_scan() {   // single block, 1024 threads, chunk=10
    __shared__ int sh[1024];
    int tid = threadIdx.x;
    int base = tid * 10;
    int cnt[10]; int local = 0;
    #pragma unroll
    for (int i = 0; i < 10; i++) {
        int idx = base + i;
        int c = (idx < NN) ? g_deg[idx] : 0;
        cnt[i] = local; local += c;
    }
    sh[tid] = local;
    __syncthreads();
    for (int off = 1; off < 1024; off <<= 1) {
        int v = (tid >= off) ? sh[tid - off] : 0;
        __syncthreads();
        sh[tid] += v;
        __syncthreads();
    }
    int start = sh[tid] - local;
    #pragma unroll
    for (int i = 0; i < 10; i++) {
        int idx = base + i;
        if (idx < NN) { g_off[idx] = start + cnt[i]; g_cursor[idx] = 0; }
    }
    if (tid == 1023) g_off[NN] = sh[1023];
}
__global__ void k_fill(const int* __restrict__ ei) {
    int e = blockIdx.x * blockDim.x + threadIdx.x;
    if (e >= EE) return;
    int s, d; edge_sd(ei, e, s, d);
    int p = atomicAdd(&g_cursor[d], 1);
    g_csr[g_off[d] + p] = s;
}

// ---------------- attention-vector & node-score kernels ----------------
__global__ void k_v1(const float* __restrict__ W1, const float* __restrict__ as,
                     const float* __restrict__ ad) {
    int r = blockIdx.x;
    int tid = threadIdx.x;
    float ss = 0.f, sd = 0.f;
    const float* wrow = W1 + (size_t)r * F1;
    for (int j = tid; j < F1; j += 256) {
        float w = wrow[j];
        ss += w * as[j];
        sd += w * ad[j];
    }
    __shared__ float s1[256], s2[256];
    s1[tid] = ss; s2[tid] = sd;
    __syncthreads();
    for (int s = 128; s > 0; s >>= 1) {
        if (tid < s) { s1[tid] += s1[tid + s]; s2[tid] += s2[tid + s]; }
        __syncthreads();
    }
    if (tid == 0) { g_v1s[r] = s1[0]; g_v1d[r] = s2[0]; }
}

__global__ void k_scores(const float* __restrict__ X, const float* __restrict__ vs,
                         const float* __restrict__ vd, int F) {
    int node = blockIdx.x;
    int tid = threadIdx.x;      // 128
    const float* xr = X + (size_t)node * F;
    float ss = 0.f, sd = 0.f;
    for (int j = tid; j < F; j += 128) {
        float x = xr[j];
        ss += x * vs[j];
        sd += x * vd[j];
    }
    __shared__ float s1[128], s2[128];
    s1[tid] = ss; s2[tid] = sd;
    __syncthreads();
    for (int s = 64; s > 0; s >>= 1) {
        if (tid < s) { s1[tid] += s1[tid + s]; s2[tid] += s2[tid + s]; }
        __syncthreads();
    }
    if (tid == 0) { g_ssrc[node] = s1[0]; g_sdst[node] = s2[0]; }
}

// ---------------- per-node softmax -> per-edge alpha (warp per node) ----------------
__global__ void k_nd() {
    int w = (blockIdx.x * blockDim.x + threadIdx.x) >> 5;
    if (w >= NN) return;
    int lane = threadIdx.x & 31;
    int rs = g_off[w], re = g_off[w + 1];
    float sdv = g_sdst[w];
    float m = -1e30f;
    for (int j = rs + lane; j < re; j += 32)
        m = fmaxf(m, lrelu(g_ssrc[g_csr[j]] + sdv));
    #pragma unroll
    for (int o = 16; o > 0; o >>= 1) m = fmaxf(m, __shfl_xor_sync(0xffffffff, m, o));
    float den = 0.f;
    for (int j = rs + lane; j < re; j += 32)
        den += __expf(lrelu(g_ssrc[g_csr[j]] + sdv) - m);
    #pragma unroll
    for (int o = 16; o > 0; o >>= 1) den += __shfl_xor_sync(0xffffffff, den, o);
    float inv = 1.0f / den;
    for (int j = rs + lane; j < re; j += 32)
        g_ew[j] = __expf(lrelu(g_ssrc[g_csr[j]] + sdv) - m) * inv;
}

// ---------------- gather aggregation (weights precomputed, no atomics) ----------------
__global__ void k_gat1(const float* __restrict__ x) {
    int n = blockIdx.x, tid = threadIdx.x;   // 128 threads
    int rs = g_off[n], re = g_off[n + 1];
    float4 acc = make_float4(0.f, 0.f, 0.f, 0.f);
    int j = rs;
    for (; j + 2 <= re; j += 2) {
        int s0 = g_csr[j], s1 = g_csr[j + 1];
        float w0 = g_ew[j], w1 = g_ew[j + 1];
        float4 v0 = ((const float4*)(x + (size_t)s0 * F0))[tid];
        float4 v1 = ((const float4*)(x + (size_t)s1 * F0))[tid];
        acc.x += w0 * v0.x; acc.y += w0 * v0.y; acc.z += w0 * v0.z; acc.w += w0 * v0.w;
        acc.x += w1 * v1.x; acc.y += w1 * v1.y; acc.z += w1 * v1.z; acc.w += w1 * v1.w;
    }
    if (j < re) {
        int s0 = g_csr[j];
        float w0 = g_ew[j];
        float4 v0 = ((const float4*)(x + (size_t)s0 * F0))[tid];
        acc.x += w0 * v0.x; acc.y += w0 * v0.y; acc.z += w0 * v0.z; acc.w += w0 * v0.w;
    }
    __half2 h0 = __floats2half2_rn(acc.x, acc.y);
    __half2 h1v = __floats2half2_rn(acc.z, acc.w);
    __half2* o = (__half2*)(g_agg1h + (size_t)n * F0);
    o[tid * 2 + 0] = h0;
    o[tid * 2 + 1] = h1v;
}

__global__ void k_gat2(const float* __restrict__ b2) {
    int n = blockIdx.x, tid = threadIdx.x;   // 256 threads
    int rs = g_off[n], re = g_off[n + 1];
    float4 acc = make_float4(0.f, 0.f, 0.f, 0.f);
    int j = rs;
    for (; j + 2 <= re; j += 2) {
        int s0 = g_csr[j], s1 = g_csr[j + 1];
        float w0 = g_ew[j], w1 = g_ew[j + 1];
        float4 v0 = ((const float4*)(g_h2 + (size_t)s0 * F2))[tid];
        float4 v1 = ((const float4*)(g_h2 + (size_t)s1 * F2))[tid];
        acc.x += w0 * v0.x; acc.y += w0 * v0.y; acc.z += w0 * v0.z; acc.w += w0 * v0.w;
        acc.x += w1 * v1.x; acc.y += w1 * v1.y; acc.z += w1 * v1.z; acc.w += w1 * v1.w;
    }
    if (j < re) {
        int s0 = g_csr[j];
        float w0 = g_ew[j];
        float4 v0 = ((const float4*)(g_h2 + (size_t)s0 * F2))[tid];
        acc.x += w0 * v0.x; acc.y += w0 * v0.y; acc.z += w0 * v0.z; acc.w += w0 * v0.w;
    }
    float4 bv = ((const float4*)b2)[tid];
    acc.x = fmaxf(acc.x + bv.x, 0.f);
    acc.y = fmaxf(acc.y + bv.y, 0.f);
    acc.z = fmaxf(acc.z + bv.z, 0.f);
    acc.w = fmaxf(acc.w + bv.w, 0.f);
    ((float4*)(g_agg2 + (size_t)n * F2))[tid] = acc;
}

// ---------------- layer 3: warp-per-node GEMM (agg2 read once) ----------------
__global__ void k_gemm3(const float* __restrict__ W3) {
    int w = (blockIdx.x * blockDim.x + threadIdx.x) >> 5;
    if (w >= NN) return;
    int lane = threadIdx.x & 31;
    const float* a = g_agg2 + (size_t)w * F2;
    float acc[F3];
    #pragma unroll
    for (int j = 0; j < F3; j++) acc[j] = 0.f;
    for (int k = lane; k < F2; k += 32) {
        float av = a[k];
        #pragma unroll
        for (int j = 0; j < F3; j++) acc[j] += av * W3[k * F3 + j];
    }
    #pragma unroll
    for (int j = 0; j < F3; j++) {
        float s = acc[j];
        #pragma unroll
        for (int o = 16; o > 0; o >>= 1) s += __shfl_xor_sync(0xffffffff, s, o);
        if (lane == 0) g_h3[w * F3 + j] = s;
    }
}

__global__ void k_gat3f(const float* __restrict__ b3, float* __restrict__ out) {
    int wg = (blockIdx.x * blockDim.x + threadIdx.x) >> 5;
    if (wg >= NN) return;
    int lane = threadIdx.x & 31;
    int rs = g_off[wg], re = g_off[wg + 1];
    float acc = 0.f;
    for (int j = rs; j < re; j++) {
        int s = g_csr[j];
        float w = g_ew[j];
        if (lane < F3) acc += w * g_h3[s * F3 + lane];
    }
    float z = (lane < F3) ? acc + b3[lane] : -1e30f;
    float mz = z;
    #pragma unroll
    for (int o = 16; o > 0; o >>= 1) mz = fmaxf(mz, __shfl_xor_sync(0xffffffff, mz, o));
    float e = (lane < F3) ? expf(z - mz) : 0.f;
    #pragma unroll
    for (int o = 16; o > 0; o >>= 1) e += __shfl_xor_sync(0xffffffff, e, o);
    float l = mz + logf(e);
    if (lane < F3) out[wg * F3 + lane] = z - l;
}

// ---------------- fp16 mma.sync GEMM, ldmatrix + 3-stage cp.async ----------------
// BM=128, BN=256, BK=64, 512 threads (16 warps, 4x4). Warp tile 32x64.
// mma m16n8k16 f16 -> 4 ks-steps per k-tile; fragments via ldmatrix.x4.
// SMEM rows padded to 72 halves = 144 B (9x16B -> 8 ldmatrix row addrs distinct banks).
#define SH_STR 72
#define ST_A_B (128 * SH_STR * 2)        // 18432 bytes
#define ST_B_B (256 * SH_STR * 2)        // 36864 bytes
#define ST_BYTES (ST_A_B + ST_B_B)       // 55296 bytes per stage
#define NSTAGE 3
#define SM_BYTES (NSTAGE * ST_BYTES)     // 165888 bytes

__device__ __forceinline__ void g_fill_async(const __half* __restrict__ A,
                                             const __half* __restrict__ Bt,
                                             uint32_t sa_u, uint32_t sb_u,
                                             int row0, int col0, int kt,
                                             int M, int K, int tid) {
    #pragma unroll
    for (int i = 0; i < 2; i++) {          // A: 128 rows x 8 chunks(16B) = 1024 / 512 thr
        int idx = i * 512 + tid;
        int m = idx >> 3, k8 = idx & 7;
        int gr = row0 + m;
        int ok = gr < M;
        const __half* src = A + (size_t)(ok ? gr : row0) * K + kt * 64 + k8 * 8;
        cpa16(sa_u + (uint32_t)(m * SH_STR + k8 * 8) * 2, src, ok ? 16 : 0);
    }
    #pragma unroll
    for (int i = 0; i < 4; i++) {          // B: 256 rows x 8 chunks = 2048 / 512 thr
        int idx = i * 512 + tid;
        int n = idx >> 3, k8 = idx & 7;
        const __half* src = Bt + (size_t)(col0 + n) * K + kt * 64 + k8 * 8;
        cpa16(sb_u + (uint32_t)(n * SH_STR + k8 * 8) * 2, src, 16);
    }
    asm volatile("cp.async.commit_group;" ::: "memory");
}

__global__ void __launch_bounds__(512, 1)
tc_gemm(const __half* __restrict__ A, const __half* __restrict__ Bt, void* __restrict__ Cv,
        int M, int Nc, int K, const float* __restrict__ bias, int doRelu, int outHalf) {
    extern __shared__ __half smh[];
    uint32_t smu = smem_u32(smh);
    int tid = threadIdx.x;
    int lane = tid & 31, wid = tid >> 5;
    int warp_m = wid & 3, warp_n = wid >> 2;   // 4 x 4
    int g = lane >> 2, c = lane & 3;
    int lr = lane & 7, lm = lane >> 3;         // ldmatrix row / matrix idx
    int row0 = blockIdx.y * 128, col0 = blockIdx.x * 256;

    // per-lane ldmatrix byte offsets (within a stage)
    uint32_t a_loff = ((uint32_t)(warp_m * 32 + lr + (lm & 1) * 8) * SH_STR
                       + ((lm >> 1) & 1) * 8) * 2;
    uint32_t b_loff = (uint32_t)ST_A_B
                      + ((uint32_t)(warp_n * 64 + lr + ((lm >> 1) & 1) * 8) * SH_STR
                         + (lm & 1) * 8) * 2;

    float acc[2][8][4];
    #pragma unroll
    for (int t = 0; t < 2; t++)
        #pragma unroll
        for (int u = 0; u < 8; u++)
            #pragma unroll
            for (int j = 0; j < 4; j++) acc[t][u][j] = 0.f;

    const int KT = K >> 6;
    g_fill_async(A, Bt, smu, smu + ST_A_B, row0, col0, 0, M, K, tid);
    if (KT > 1)
        g_fill_async(A, Bt, smu + ST_BYTES, smu + ST_BYTES + ST_A_B, row0, col0, 1, M, K, tid);

    for (int kt = 0; kt < KT; kt++) {
        int buf = kt % NSTAGE;
        if (kt + 2 < KT) {
            int nb = (kt + 2) % NSTAGE;
            g_fill_async(A, Bt, smu + nb * ST_BYTES, smu + nb * ST_BYTES + ST_A_B,
                         row0, col0, kt + 2, M, K, tid);
            asm volatile("cp.async.wait_group 2;" ::: "memory");
        } else if (kt + 1 < KT) {
            asm volatile("cp.async.wait_group 1;" ::: "memory");
        } else {
            asm volatile("cp.async.wait_group 0;" ::: "memory");
        }
        __syncthreads();
        uint32_t st = smu + buf * ST_BYTES;
        #pragma unroll
        for (int ks = 0; ks < 4; ks++) {
            uint32_t af[2][4];
            #pragma unroll
            for (int t = 0; t < 2; t++)
                ldm4(af[t], st + a_loff + (uint32_t)(t * 16 * SH_STR * 2) + ks * 32);
            uint32_t bf[8][2];
            #pragma unroll
            for (int p = 0; p < 4; p++) {
                uint32_t r4[4];
                ldm4(r4, st + b_loff + (uint32_t)(p * 16 * SH_STR * 2) + ks * 32);
                bf[p * 2][0] = r4[0];     bf[p * 2][1] = r4[1];
                bf[p * 2 + 1][0] = r4[2]; bf[p * 2 + 1][1] = r4[3];
            }
            #pragma unroll
            for (int t = 0; t < 2; t++)
                #pragma unroll
                for (int u = 0; u < 8; u++)
                    mma16(acc[t][u], af[t], bf[u]);
        }
        __syncthreads();
    }

    // epilogue
    #pragma unroll
    for (int t = 0; t < 2; t++) {
        int r0 = row0 + warp_m * 32 + t * 16 + g;
        #pragma unroll
        for (int u = 0; u < 8; u++) {
            int cc = col0 + warp_n * 64 + u * 8 + 2 * c;
            float2 v0 = make_float2(acc[t][u][0], acc[t][u][1]);
            float2 v1 = make_float2(acc[t][u][2], acc[t][u][3]);
            if (bias) {
                float b0v = bias[cc], b1v = bias[cc + 1];
                v0.x += b0v; v0.y += b1v;
                v1.x += b0v; v1.y += b1v;
            }
            if (doRelu) {
                v0.x = fmaxf(v0.x, 0.f); v0.y = fmaxf(v0.y, 0.f);
                v1.x = fmaxf(v1.x, 0.f); v1.y = fmaxf(v1.y, 0.f);
            }
            if (outHalf) {
                __half* C = (__half*)Cv;
                if (r0 < M)
                    *(__half2*)(C + (size_t)r0 * Nc + cc) = __floats2half2_rn(v0.x, v0.y);
                if (r0 + 8 < M)
                    *(__half2*)(C + (size_t)(r0 + 8) * Nc + cc) = __floats2half2_rn(v1.x, v1.y);
            } else {
                float* C = (float*)Cv;
                if (r0 < M)     *(float2*)(C + (size_t)r0 * Nc + cc) = v0;
                if (r0 + 8 < M) *(float2*)(C + (size_t)(r0 + 8) * Nc + cc) = v1;
            }
        }
    }
}

// ---------------- launch ----------------
extern "C" void kernel_launch(void* const* d_in, const int* in_sizes, int n_in,
                              void* d_out, int out_size) {
    const float* x   = (const float*)d_in[0];
    const int*   ei  = (const int*)d_in[1];
    const float* W1  = (const float*)d_in[2];
    const float* as1 = (const float*)d_in[3];
    const float* ad1 = (const float*)d_in[4];
    const float* b1  = (const float*)d_in[5];
    const float* W2  = (const float*)d_in[6];
    const float* as2 = (const float*)d_in[7];
    const float* ad2 = (const float*)d_in[8];
    const float* b2  = (const float*)d_in[9];
    const float* W3  = (const float*)d_in[10];
    const float* as3 = (const float*)d_in[11];
    const float* ad3 = (const float*)d_in[12];
    const float* b3  = (const float*)d_in[13];
    float* out = (float*)d_out;

    void *p_agg1h, *p_agg2, *p_h1h, *p_h2, *p_h3, *p_v1s, *p_v1d, *p_w1t, *p_w2t;
    cudaGetSymbolAddress(&p_agg1h, g_agg1h);
    cudaGetSymbolAddress(&p_agg2, g_agg2);
    cudaGetSymbolAddress(&p_h1h, g_h1h);
    cudaGetSymbolAddress(&p_h2, g_h2);
    cudaGetSymbolAddress(&p_h3, g_h3);
    cudaGetSymbolAddress(&p_v1s, g_v1s);
    cudaGetSymbolAddress(&p_v1d, g_v1d);
    cudaGetSymbolAddress(&p_w1t, g_w1t);
    cudaGetSymbolAddress(&p_w2t, g_w2t);

    cudaFuncSetAttribute(tc_gemm, cudaFuncAttributeMaxDynamicSharedMemorySize, SM_BYTES);

    const int EB = (EE + 255) / 256;
    const int MB128 = (NN + 127) / 128;
    const int NWB = (NN * 32 + 255) / 256;   // warp-per-node grids

    // ---- weight transpose + fp16 convert (once, independent) ----
    k_transpose_h<<<dim3(F1 / 32, F0 / 32), dim3(32, 8)>>>(W1, (__half*)p_w1t, F0, F1);
    k_transpose_h<<<dim3(F2 / 32, F1 / 32), dim3(32, 8)>>>(W2, (__half*)p_w2t, F1, F2);

    // ---- CSR build (reused by all 3 layers) ----
    k_zerodeg<<<(NN + 255) / 256, 256>>>();
    k_deg<<<EB, 256>>>(ei);
    k_scan<<<1, 1024>>>();
    k_fill<<<EB, 256>>>(ei);

    // ---- Layer 1: scores on x, alpha, gather (->half), GEMM ----
    k_v1<<<F0, 256>>>(W1, as1, ad1);
    k_scores<<<NN, 128>>>(x, (const float*)p_v1s, (const float*)p_v1d, F0);
    k_nd<<<NWB, 256>>>();
    k_gat1<<<NN, 128>>>(x);
    {
        dim3 grd(F1 / 256, MB128);
        tc_gemm<<<grd, 512, SM_BYTES>>>((const __half*)p_agg1h, (const __half*)p_w1t,
                                        p_h1h, NN, F1, F0, b1, 1, 1);
    }

    // ---- Layer 2: GEMM (BM=128, minimal B re-reads), scores, alpha, gather ----
    {
        dim3 grd(F2 / 256, MB128);
        tc_gemm<<<grd, 512, SM_BYTES>>>((const __half*)p_h1h, (const __half*)p_w2t,
                                        p_h2, NN, F2, F1, nullptr, 0, 0);
    }
    k_scores<<<NN, 128>>>((const float*)p_h2, as2, ad2, F2);
    k_nd<<<NWB, 256>>>();
    k_gat2<<<NN, 256>>>(b2);

    // ---- Layer 3: warp-per-node GEMM, scores, alpha, fused gather+log_softmax ----
    k_gemm3<<<NWB, 256>>>(W3);
    k_scores<<<NN, 128>>>((const float*)p_h3, as3, ad3, F3);
    k_nd<<<NWB, 256>>>();
    k_gat3f<<<NWB, 256>>>(b3, out);
}

// round 14
// speedup vs baseline: 1.0726x; 1.0094x over previous
#include <cuda_runtime.h>
#include <cuda_fp16.h>
#include <math.h>
#include <stdint.h>

#define NN 10000
#define E0 80000
#define EE 90000
#define F0 512
#define F1 4096
#define F2 1024
#define F3 7
#define NSLOPE 0.2f

// ---------------- scratch (static device globals; no allocation) ----------------
__device__ __half g_agg1h[(size_t)NN * F0];     // half agg (A of GEMM1)
__device__ __half g_h1h[(size_t)NN * F1];       // half h1 (A of GEMM2)
__device__ __half g_h2h[(size_t)NN * F2];       // half h2 (GEMM2 out)
__device__ float  g_agg2[(size_t)NN * F2];
__device__ float  g_h3[NN * F3];
__device__ float  g_ssrc[NN], g_sdst[NN];
__device__ float  g_v1s[F0], g_v1d[F0];
__device__ __half g_w1t[(size_t)F1 * F0];       // W1^T half [N][K]
__device__ __half g_w2t[(size_t)F2 * F1];       // W2^T half [N][K]
__device__ float  g_ew[EE];                     // per-edge alpha (per layer)
// CSR by destination
__device__ int g_deg[NN];
__device__ int g_cursor[NN];
__device__ int g_off[NN + 1];
__device__ int g_csr[EE];

__device__ __forceinline__ void edge_sd(const int* __restrict__ ei, int e, int& s, int& d) {
    if (e < E0) { s = ei[e]; d = ei[E0 + e]; }
    else        { s = e - E0; d = e - E0; }
}
__device__ __forceinline__ uint32_t smem_u32(const void* p) {
    uint32_t a;
    asm("{ .reg .u64 t; cvta.to.shared.u64 t, %1; cvt.u32.u64 %0, t; }" : "=r"(a) : "l"(p));
    return a;
}
__device__ __forceinline__ void cpa16(uint32_t dst, const void* src, int sz) {
    asm volatile("cp.async.cg.shared.global [%0], [%1], 16, %2;"
                 :: "r"(dst), "l"(src), "r"(sz));
}
__device__ __forceinline__ void mma16(float* c, const uint32_t* a, const uint32_t* b) {
    asm volatile(
        "mma.sync.aligned.m16n8k16.row.col.f32.f16.f16.f32 "
        "{%0,%1,%2,%3}, {%4,%5,%6,%7}, {%8,%9}, {%0,%1,%2,%3};"
        : "+f"(c[0]), "+f"(c[1]), "+f"(c[2]), "+f"(c[3])
        : "r"(a[0]), "r"(a[1]), "r"(a[2]), "r"(a[3]), "r"(b[0]), "r"(b[1]));
}
__device__ __forceinline__ void ldm4(uint32_t* r, uint32_t addr) {
    asm volatile("ldmatrix.sync.aligned.m8n8.x4.shared.b16 {%0,%1,%2,%3}, [%4];"
                 : "=r"(r[0]), "=r"(r[1]), "=r"(r[2]), "=r"(r[3]) : "r"(addr));
}
__device__ __forceinline__ float lrelu(float v) { return (v > 0.f) ? v : NSLOPE * v; }

// ---------------- weight transpose + fp16 convert: out[n][k] = half(in[k][n]) ----------------
__global__ void k_transpose_h(const float* __restrict__ in, __half* __restrict__ out,
                              int K, int N) {
    __shared__ __half tile[32][34];
    int n0 = blockIdx.x * 32, k0 = blockIdx.y * 32;
    int tx = threadIdx.x, ty = threadIdx.y;   // 32 x 8
    #pragma unroll
    for (int i = 0; i < 4; i++) {
        int k = k0 + ty + i * 8;
        tile[ty + i * 8][tx] = __float2half_rn(in[(size_t)k * N + n0 + tx]);
    }
    __syncthreads();
    #pragma unroll
    for (int i = 0; i < 4; i++) {
        int n = n0 + ty + i * 8;
        out[(size_t)n * K + k0 + tx] = tile[tx][ty + i * 8];
    }
}

// ---------------- CSR build ----------------
__global__ void k_zerodeg() {
    int i = blockIdx.x * blockDim.x + threadIdx.x;
    if (i < NN) g_deg[i] = 0;
}
__global__ void k_deg(const int* __restrict__ ei) {
    int e = blockIdx.x * blockDim.x + threadIdx.x;
    if (e >= EE) return;
    int s, d; edge_sd(ei, e, s, d);
    atomicAdd(&g_deg[d], 1);
}
__global__ void k_scan() {   // single block, 1024 threads, chunk=10
    __shared__ int sh[1024];
    int tid = threadIdx.x;
    int base = tid * 10;
    int cnt[10]; int local = 0;
    #pragma unroll
    for (int i = 0; i < 10; i++) {
        int idx = base + i;
        int c = (idx < NN) ? g_deg[idx] : 0;
        cnt[i] = local; local += c;
    }
    sh[tid] = local;
    __syncthreads();
    for (int off = 1; off < 1024; off <<= 1) {
        int v = (tid >= off) ? sh[tid - off] : 0;
        __syncthreads();
        sh[tid] += v;
        __syncthreads();
    }
    int start = sh[tid] - local;
    #pragma unroll
    for (int i = 0; i < 10; i++) {
        int idx = base + i;
        if (idx < NN) { g_off[idx] = start + cnt[i]; g_cursor[idx] = 0; }
    }
    if (tid == 1023) g_off[NN] = sh[1023];
}
__global__ void k_fill(const int* __restrict__ ei) {
    int e = blockIdx.x * blockDim.x + threadIdx.x;
    if (e >= EE) return;
    int s, d; edge_sd(ei, e, s, d);
    int p = atomicAdd(&g_cursor[d], 1);
    g_csr[g_off[d] + p] = s;
}

// ---------------- attention-vector & node-score kernels ----------------
__global__ void k_v1(const float* __restrict__ W1, const float* __restrict__ as,
                     const float* __restrict__ ad) {
    int r = blockIdx.x;
    int tid = threadIdx.x;
    float ss = 0.f, sd = 0.f;
    const float* wrow = W1 + (size_t)r * F1;
    for (int j = tid; j < F1; j += 256) {
        float w = wrow[j];
        ss += w * as[j];
        sd += w * ad[j];
    }
    __shared__ float s1[256], s2[256];
    s1[tid] = ss; s2[tid] = sd;
    __syncthreads();
    for (int s = 128; s > 0; s >>= 1) {
        if (tid < s) { s1[tid] += s1[tid + s]; s2[tid] += s2[tid + s]; }
        __syncthreads();
    }
    if (tid == 0) { g_v1s[r] = s1[0]; g_v1d[r] = s2[0]; }
}

__global__ void k_scores(const float* __restrict__ X, const float* __restrict__ vs,
                         const float* __restrict__ vd, int F) {
    int node = blockIdx.x;
    int tid = threadIdx.x;      // 128
    const float* xr = X + (size_t)node * F;
    float ss = 0.f, sd = 0.f;
    for (int j = tid; j < F; j += 128) {
        float x = xr[j];
        ss += x * vs[j];
        sd += x * vd[j];
    }
    __shared__ float s1[128], s2[128];
    s1[tid] = ss; s2[tid] = sd;
    __syncthreads();
    for (int s = 64; s > 0; s >>= 1) {
        if (tid < s) { s1[tid] += s1[tid + s]; s2[tid] += s2[tid + s]; }
        __syncthreads();
    }
    if (tid == 0) { g_ssrc[node] = s1[0]; g_sdst[node] = s2[0]; }
}

// half-input scores (for h2)
__global__ void k_scores_h(const __half* __restrict__ X, const float* __restrict__ vs,
                           const float* __restrict__ vd, int F) {
    int node = blockIdx.x;
    int tid = threadIdx.x;      // 128
    const __half2* xr = (const __half2*)(X + (size_t)node * F);
    int F2h = F >> 1;
    float ss = 0.f, sd = 0.f;
    for (int j = tid; j < F2h; j += 128) {
        float2 x2 = __half22float2(xr[j]);
        ss += x2.x * vs[2 * j] + x2.y * vs[2 * j + 1];
        sd += x2.x * vd[2 * j] + x2.y * vd[2 * j + 1];
    }
    __shared__ float s1[128], s2[128];
    s1[tid] = ss; s2[tid] = sd;
    __syncthreads();
    for (int s = 64; s > 0; s >>= 1) {
        if (tid < s) { s1[tid] += s1[tid + s]; s2[tid] += s2[tid + s]; }
        __syncthreads();
    }
    if (tid == 0) { g_ssrc[node] = s1[0]; g_sdst[node] = s2[0]; }
}

// ---------------- per-node softmax -> per-edge alpha (warp per node) ----------------
__global__ void k_nd() {
    int w = (blockIdx.x * blockDim.x + threadIdx.x) >> 5;
    if (w >= NN) return;
    int lane = threadIdx.x & 31;
    int rs = g_off[w], re = g_off[w + 1];
    float sdv = g_sdst[w];
    float m = -1e30f;
    for (int j = rs + lane; j < re; j += 32)
        m = fmaxf(m, lrelu(g_ssrc[g_csr[j]] + sdv));
    #pragma unroll
    for (int o = 16; o > 0; o >>= 1) m = fmaxf(m, __shfl_xor_sync(0xffffffff, m, o));
    float den = 0.f;
    for (int j = rs + lane; j < re; j += 32)
        den += __expf(lrelu(g_ssrc[g_csr[j]] + sdv) - m);
    #pragma unroll
    for (int o = 16; o > 0; o >>= 1) den += __shfl_xor_sync(0xffffffff, den, o);
    float inv = 1.0f / den;
    for (int j = rs + lane; j < re; j += 32)
        g_ew[j] = __expf(lrelu(g_ssrc[g_csr[j]] + sdv) - m) * inv;
}

// ---------------- gather aggregation (weights precomputed, no atomics) ----------------
__global__ void k_gat1(const float* __restrict__ x) {
    int n = blockIdx.x, tid = threadIdx.x;   // 128 threads
    int rs = g_off[n], re = g_off[n + 1];
    float4 acc = make_float4(0.f, 0.f, 0.f, 0.f);
    int j = rs;
    for (; j + 2 <= re; j += 2) {
        int s0 = g_csr[j], s1 = g_csr[j + 1];
        float w0 = g_ew[j], w1 = g_ew[j + 1];
        float4 v0 = ((const float4*)(x + (size_t)s0 * F0))[tid];
        float4 v1 = ((const float4*)(x + (size_t)s1 * F0))[tid];
        acc.x += w0 * v0.x; acc.y += w0 * v0.y; acc.z += w0 * v0.z; acc.w += w0 * v0.w;
        acc.x += w1 * v1.x; acc.y += w1 * v1.y; acc.z += w1 * v1.z; acc.w += w1 * v1.w;
    }
    if (j < re) {
        int s0 = g_csr[j];
        float w0 = g_ew[j];
        float4 v0 = ((const float4*)(x + (size_t)s0 * F0))[tid];
        acc.x += w0 * v0.x; acc.y += w0 * v0.y; acc.z += w0 * v0.z; acc.w += w0 * v0.w;
    }
    __half2 h0 = __floats2half2_rn(acc.x, acc.y);
    __half2 h1v = __floats2half2_rn(acc.z, acc.w);
    __half2* o = (__half2*)(g_agg1h + (size_t)n * F0);
    o[tid * 2 + 0] = h0;
    o[tid * 2 + 1] = h1v;
}

__global__ void k_gat2(const float* __restrict__ b2) {
    int n = blockIdx.x, tid = threadIdx.x;   // 256 threads, 4 halves each
    int rs = g_off[n], re = g_off[n + 1];
    float4 acc = make_float4(0.f, 0.f, 0.f, 0.f);
    int j = rs;
    for (; j + 2 <= re; j += 2) {
        int s0 = g_csr[j], s1 = g_csr[j + 1];
        float w0 = g_ew[j], w1 = g_ew[j + 1];
        uint2 u0 = ((const uint2*)(g_h2h + (size_t)s0 * F2))[tid];
        uint2 u1 = ((const uint2*)(g_h2h + (size_t)s1 * F2))[tid];
        float2 a0 = __half22float2(*(__half2*)&u0.x);
        float2 a1 = __half22float2(*(__half2*)&u0.y);
        float2 b0v = __half22float2(*(__half2*)&u1.x);
        float2 b1v = __half22float2(*(__half2*)&u1.y);
        acc.x += w0 * a0.x; acc.y += w0 * a0.y; acc.z += w0 * a1.x; acc.w += w0 * a1.y;
        acc.x += w1 * b0v.x; acc.y += w1 * b0v.y; acc.z += w1 * b1v.x; acc.w += w1 * b1v.y;
    }
    if (j < re) {
        int s0 = g_csr[j];
        float w0 = g_ew[j];
        uint2 u0 = ((const uint2*)(g_h2h + (size_t)s0 * F2))[tid];
        float2 a0 = __half22float2(*(__half2*)&u0.x);
        float2 a1 = __half22float2(*(__half2*)&u0.y);
        acc.x += w0 * a0.x; acc.y += w0 * a0.y; acc.z += w0 * a1.x; acc.w += w0 * a1.y;
    }
    float4 bv = ((const float4*)b2)[tid];
    acc.x = fmaxf(acc.x + bv.x, 0.f);
    acc.y = fmaxf(acc.y + bv.y, 0.f);
    acc.z = fmaxf(acc.z + bv.z, 0.f);
    acc.w = fmaxf(acc.w + bv.w, 0.f);
    ((float4*)(g_agg2 + (size_t)n * F2))[tid] = acc;
}

// ---------------- layer 3: warp-per-node GEMM + fused scores ----------------
__global__ void k_gemm3(const float* __restrict__ W3, const float* __restrict__ as3,
                        const float* __restrict__ ad3) {
    int w = (blockIdx.x * blockDim.x + threadIdx.x) >> 5;
    if (w >= NN) return;
    int lane = threadIdx.x & 31;
    const float* a = g_agg2 + (size_t)w * F2;
    float acc[F3];
    #pragma unroll
    for (int j = 0; j < F3; j++) acc[j] = 0.f;
    for (int k = lane; k < F2; k += 32) {
        float av = a[k];
        #pragma unroll
        for (int j = 0; j < F3; j++) acc[j] += av * W3[k * F3 + j];
    }
    float ss = 0.f, sd = 0.f;
    #pragma unroll
    for (int j = 0; j < F3; j++) {
        float s = acc[j];
        #pragma unroll
        for (int o = 16; o > 0; o >>= 1) s += __shfl_xor_sync(0xffffffff, s, o);
        if (lane == 0) g_h3[w * F3 + j] = s;
        ss += s * as3[j];
        sd += s * ad3[j];
    }
    if (lane == 0) { g_ssrc[w] = ss; g_sdst[w] = sd; }
}

__global__ void k_gat3f(const float* __restrict__ b3, float* __restrict__ out) {
    int wg = (blockIdx.x * blockDim.x + threadIdx.x) >> 5;
    if (wg >= NN) return;
    int lane = threadIdx.x & 31;
    int rs = g_off[wg], re = g_off[wg + 1];
    float acc = 0.f;
    for (int j = rs; j < re; j++) {
        int s = g_csr[j];
        float w = g_ew[j];
        if (lane < F3) acc += w * g_h3[s * F3 + lane];
    }
    float z = (lane < F3) ? acc + b3[lane] : -1e30f;
    float mz = z;
    #pragma unroll
    for (int o = 16; o > 0; o >>= 1) mz = fmaxf(mz, __shfl_xor_sync(0xffffffff, mz, o));
    float e = (lane < F3) ? expf(z - mz) : 0.f;
    #pragma unroll
    for (int o = 16; o > 0; o >>= 1) e += __shfl_xor_sync(0xffffffff, e, o);
    float l = mz + logf(e);
    if (lane < F3) out[wg * F3 + lane] = z - l;
}

// ---------------- fp16 mma.sync GEMM, ldmatrix + 3-stage cp.async (templated) ----------------
// WMW warps in M, WNW warps in N, NU n8-tiles per warp. BM=WMW*32, BN=WNW*NU*8.
// Warp tile = 32 x NU*8 (2 m16 x NU n8). SMEM rows padded to 72 halves = 144 B.
#define SH_STR 72
#define NSTAGE 3

template<int WMW, int WNW, int NU>
__global__ void __launch_bounds__(WMW * WNW * 32, 1)
tc_gemm(const __half* __restrict__ A, const __half* __restrict__ Bt, void* __restrict__ Cv,
        int M, int Nc, int K, const float* __restrict__ bias, int doRelu, int outHalf) {
    constexpr int THREADS = WMW * WNW * 32;
    constexpr int BM = WMW * 32;
    constexpr int WNC = NU * 8;
    constexpr int BN = WNW * WNC;
    constexpr int STA = BM * SH_STR * 2;
    constexpr int STB = BN * SH_STR * 2;
    constexpr int STBY = STA + STB;
    constexpr int ACH = BM * 8;           // 16B chunks in A tile
    constexpr int BCH = BN * 8;

    extern __shared__ __half smh[];
    uint32_t smu = smem_u32(smh);
    int tid = threadIdx.x;
    int lane = tid & 31, wid = tid >> 5;
    int warp_m = wid % WMW, warp_n = wid / WMW;
    int g = lane >> 2, c = lane & 3;
    int lr = lane & 7, lm = lane >> 3;
    int row0 = blockIdx.y * BM, col0 = blockIdx.x * BN;

    uint32_t a_loff = ((uint32_t)(warp_m * 32 + lr + (lm & 1) * 8) * SH_STR
                       + ((lm >> 1) & 1) * 8) * 2;
    uint32_t b_loff = (uint32_t)STA
                      + ((uint32_t)(warp_n * WNC + lr + ((lm >> 1) & 1) * 8) * SH_STR
                         + (lm & 1) * 8) * 2;

    float acc[2][NU][4];
    #pragma unroll
    for (int t = 0; t < 2; t++)
        #pragma unroll
        for (int u = 0; u < NU; u++)
            #pragma unroll
            for (int j = 0; j < 4; j++) acc[t][u][j] = 0.f;

    const int KT = K >> 6;

    auto fill = [&](int kt, int stage) {
        uint32_t sa_u = smu + stage * STBY;
        uint32_t sb_u = sa_u + STA;
        #pragma unroll
        for (int i = 0; i < (ACH + THREADS - 1) / THREADS; i++) {
            int idx = i * THREADS + tid;
            if ((ACH % THREADS) == 0 || idx < ACH) {
                int m = idx >> 3, k8 = idx & 7;
                int gr = row0 + m;
                int ok = gr < M;
                const __half* src = A + (size_t)(ok ? gr : row0) * K + kt * 64 + k8 * 8;
                cpa16(sa_u + (uint32_t)(m * SH_STR + k8 * 8) * 2, src, ok ? 16 : 0);
            }
        }
        #pragma unroll
        for (int i = 0; i < (BCH + THREADS - 1) / THREADS; i++) {
            int idx = i * THREADS + tid;
            if ((BCH % THREADS) == 0 || idx < BCH) {
                int n = idx >> 3, k8 = idx & 7;
                const __half* src = Bt + (size_t)(col0 + n) * K + kt * 64 + k8 * 8;
                cpa16(sb_u + (uint32_t)(n * SH_STR + k8 * 8) * 2, src, 16);
            }
        }
        asm volatile("cp.async.commit_group;" ::: "memory");
    };

    fill(0, 0);
    if (KT > 1) fill(1, 1);

    for (int kt = 0; kt < KT; kt++) {
        int buf = kt % NSTAGE;
        if (kt + 2 < KT) {
            fill(kt + 2, (kt + 2) % NSTAGE);
            asm volatile("cp.async.wait_group 2;" ::: "memory");
        } else if (kt + 1 < KT) {
            asm volatile("cp.async.wait_group 1;" ::: "memory");
        } else {
            asm volatile("cp.async.wait_group 0;" ::: "memory");
        }
        __syncthreads();
        uint32_t st = smu + buf * STBY;
        #pragma unroll
        for (int ks = 0; ks < 4; ks++) {
            uint32_t af[2][4];
            #pragma unroll
            for (int t = 0; t < 2; t++)
                ldm4(af[t], st + a_loff + (uint32_t)(t * 16 * SH_STR * 2) + ks * 32);
            uint32_t bf[NU][2];
            #pragma unroll
            for (int p = 0; p < NU / 2; p++) {
                uint32_t r4[4];
                ldm4(r4, st + b_loff + (uint32_t)(p * 16 * SH_STR * 2) + ks * 32);
                bf[p * 2][0] = r4[0];     bf[p * 2][1] = r4[1];
                bf[p * 2 + 1][0] = r4[2]; bf[p * 2 + 1][1] = r4[3];
            }
            #pragma unroll
            for (int t = 0; t < 2; t++)
                #pragma unroll
                for (int u = 0; u < NU; u++)
                    mma16(acc[t][u], af[t], bf[u]);
        }
        __syncthreads();
    }

    // epilogue
    #pragma unroll
    for (int t = 0; t < 2; t++) {
        int r0 = row0 + warp_m * 32 + t * 16 + g;
        #pragma unroll
        for (int u = 0; u < NU; u++) {
            int cc = col0 + warp_n * WNC + u * 8 + 2 * c;
            float2 v0 = make_float2(acc[t][u][0], acc[t][u][1]);
            float2 v1 = make_float2(acc[t][u][2], acc[t][u][3]);
            if (bias) {
                float b0v = bias[cc], b1v = bias[cc + 1];
                v0.x += b0v; v0.y += b1v;
                v1.x += b0v; v1.y += b1v;
            }
            if (doRelu) {
                v0.x = fmaxf(v0.x, 0.f); v0.y = fmaxf(v0.y, 0.f);
                v1.x = fmaxf(v1.x, 0.f); v1.y = fmaxf(v1.y, 0.f);
            }
            if (outHalf) {
                __half* C = (__half*)Cv;
                if (r0 < M)
                    *(__half2*)(C + (size_t)r0 * Nc + cc) = __floats2half2_rn(v0.x, v0.y);
                if (r0 + 8 < M)
                    *(__half2*)(C + (size_t)(r0 + 8) * Nc + cc) = __floats2half2_rn(v1.x, v1.y);
            } else {
                float* C = (float*)Cv;
                if (r0 < M)     *(float2*)(C + (size_t)r0 * Nc + cc) = v0;
                if (r0 + 8 < M) *(float2*)(C + (size_t)(r0 + 8) * Nc + cc) = v1;
            }
        }
    }
}

// GEMM1: 4x4 warps, NU=8 -> BM=128, BN=256, 512 thr. Stage 55296 B -> 165888.
// GEMM2: 5x4 warps, NU=4 -> BM=160, BN=128, 640 thr. Stage 41472 B -> 124416.
#define SMB_G1 (NSTAGE * (128 * SH_STR * 2 + 256 * SH_STR * 2))
#define SMB_G2 (NSTAGE * (160 * SH_STR * 2 + 128 * SH_STR * 2))

// ---------------- launch ----------------
extern "C" void kernel_launch(void* const* d_in, const int* in_sizes, int n_in,
                              void* d_out, int out_size) {
    const float* x   = (const float*)d_in[0];
    const int*   ei  = (const int*)d_in[1];
    const float* W1  = (const float*)d_in[2];
    const float* as1 = (const float*)d_in[3];
    const float* ad1 = (const float*)d_in[4];
    const float* b1  = (const float*)d_in[5];
    const float* W2  = (const float*)d_in[6];
    const float* as2 = (const float*)d_in[7];
    const float* ad2 = (const float*)d_in[8];
    const float* b2  = (const float*)d_in[9];
    const float* W3  = (const float*)d_in[10];
    const float* as3 = (const float*)d_in[11];
    const float* ad3 = (const float*)d_in[12];
    const float* b3  = (const float*)d_in[13];
    float* out = (float*)d_out;

    void *p_agg1h, *p_h1h, *p_h2h, *p_v1s, *p_v1d, *p_w1t, *p_w2t;
    cudaGetSymbolAddress(&p_agg1h, g_agg1h);
    cudaGetSymbolAddress(&p_h1h, g_h1h);
    cudaGetSymbolAddress(&p_h2h, g_h2h);
    cudaGetSymbolAddress(&p_v1s, g_v1s);
    cudaGetSymbolAddress(&p_v1d, g_v1d);
    cudaGetSymbolAddress(&p_w1t, g_w1t);
    cudaGetSymbolAddress(&p_w2t, g_w2t);

    cudaFuncSetAttribute(tc_gemm<4, 4, 8>, cudaFuncAttributeMaxDynamicSharedMemorySize, SMB_G1);
    cudaFuncSetAttribute(tc_gemm<5, 4, 4>, cudaFuncAttributeMaxDynamicSharedMemorySize, SMB_G2);

    const int EB = (EE + 255) / 256;
    const int NWB = (NN * 32 + 255) / 256;   // warp-per-node grids

    // ---- weight transpose + fp16 convert (once, independent) ----
    k_transpose_h<<<dim3(F1 / 32, F0 / 32), dim3(32, 8)>>>(W1, (__half*)p_w1t, F0, F1);
    k_transpose_h<<<dim3(F2 / 32, F1 / 32), dim3(32, 8)>>>(W2, (__half*)p_w2t, F1, F2);

    // ---- CSR build (reused by all 3 layers) ----
    k_zerodeg<<<(NN + 255) / 256, 256>>>();
    k_deg<<<EB, 256>>>(ei);
    k_scan<<<1, 1024>>>();
    k_fill<<<EB, 256>>>(ei);

    // ---- Layer 1: scores on x, alpha, gather (->half), GEMM ----
    k_v1<<<F0, 256>>>(W1, as1, ad1);
    k_scores<<<NN, 128>>>(x, (const float*)p_v1s, (const float*)p_v1d, F0);
    k_nd<<<NWB, 256>>>();
    k_gat1<<<NN, 128>>>(x);
    {
        dim3 grd(F1 / 256, (NN + 127) / 128);
        tc_gemm<4, 4, 8><<<grd, 512, SMB_G1>>>((const __half*)p_agg1h, (const __half*)p_w1t,
                                               p_h1h, NN, F1, F0, b1, 1, 1);
    }

    // ---- Layer 2: GEMM (BM=160/BN=128, wave-fit; half out), scores, alpha, gather ----
    {
        dim3 grd(F2 / 128, (NN + 159) / 160);
        tc_gemm<5, 4, 4><<<grd, 640, SMB_G2>>>((const __half*)p_h1h, (const __half*)p_w2t,
                                               p_h2h, NN, F2, F1, nullptr, 0, 1);
    }
    k_scores_h<<<NN, 128>>>((const __half*)p_h2h, as2, ad2, F2);
    k_nd<<<NWB, 256>>>();
    k_gat2<<<NN, 256>>>(b2);

    // ---- Layer 3: warp-per-node GEMM (+fused scores), alpha, gather+log_softmax ----
    k_gemm3<<<NWB, 256>>>(W3, as3, ad3);
    k_nd<<<NWB, 256>>>();
    k_gat3f<<<NWB, 256>>>(b3, out);
}

// round 15
// speedup vs baseline: 1.0874x; 1.0137x over previous
#include <cuda_runtime.h>
#include <cuda_fp16.h>
#include <math.h>
#include <stdint.h>

#define NN 10000
#define E0 80000
#define EE 90000
#define F0 512
#define F1 4096
#define F2 1024
#define F3 7
#define NSLOPE 0.2f

// ---------------- scratch (static device globals; no allocation) ----------------
__device__ __half g_xh[(size_t)NN * F0];        // half copy of x (gather source)
__device__ __half g_agg1h[(size_t)NN * F0];     // half agg (A of GEMM1)
__device__ __half g_h1h[(size_t)NN * F1];       // half h1 (A of GEMM2)
__device__ __half g_h2h[(size_t)NN * F2];       // half h2 (GEMM2 out)
__device__ float  g_agg2[(size_t)NN * F2];
__device__ float  g_h3[NN * F3];
__device__ float  g_ssrc[NN], g_sdst[NN];
__device__ float  g_v1s[F0], g_v1d[F0];
__device__ __half g_w1t[(size_t)F1 * F0];       // W1^T half [N][K]
__device__ __half g_w2t[(size_t)F2 * F1];       // W2^T half [N][K]
__device__ float  g_ew[EE];                     // per-edge alpha (per layer)
// CSR by destination
__device__ int g_deg[NN];
__device__ int g_cursor[NN];
__device__ int g_off[NN + 1];
__device__ int g_csr[EE];

__device__ __forceinline__ void edge_sd(const int* __restrict__ ei, int e, int& s, int& d) {
    if (e < E0) { s = ei[e]; d = ei[E0 + e]; }
    else        { s = e - E0; d = e - E0; }
}
__device__ __forceinline__ uint32_t smem_u32(const void* p) {
    uint32_t a;
    asm("{ .reg .u64 t; cvta.to.shared.u64 t, %1; cvt.u32.u64 %0, t; }" : "=r"(a) : "l"(p));
    return a;
}
__device__ __forceinline__ void cpa16(uint32_t dst, const void* src, int sz) {
    asm volatile("cp.async.cg.shared.global [%0], [%1], 16, %2;"
                 :: "r"(dst), "l"(src), "r"(sz));
}
__device__ __forceinline__ void mma16(float* c, const uint32_t* a, const uint32_t* b) {
    asm volatile(
        "mma.sync.aligned.m16n8k16.row.col.f32.f16.f16.f32 "
        "{%0,%1,%2,%3}, {%4,%5,%6,%7}, {%8,%9}, {%0,%1,%2,%3};"
        : "+f"(c[0]), "+f"(c[1]), "+f"(c[2]), "+f"(c[3])
        : "r"(a[0]), "r"(a[1]), "r"(a[2]), "r"(a[3]), "r"(b[0]), "r"(b[1]));
}
__device__ __forceinline__ void ldm4(uint32_t* r, uint32_t addr) {
    asm volatile("ldmatrix.sync.aligned.m8n8.x4.shared.b16 {%0,%1,%2,%3}, [%4];"
                 : "=r"(r[0]), "=r"(r[1]), "=r"(r[2]), "=r"(r[3]) : "r"(addr));
}
__device__ __forceinline__ float lrelu(float v) { return (v > 0.f) ? v : NSLOPE * v; }

// ---------------- x -> half conversion ----------------
__global__ void k_xh(const float* __restrict__ x) {
    long n2 = (long)NN * F0 / 2;
    long i = (long)blockIdx.x * blockDim.x + threadIdx.x;
    long stride = (long)gridDim.x * blockDim.x;
    for (; i < n2; i += stride) {
        float2 v = ((const float2*)x)[i];
        ((__half2*)g_xh)[i] = __floats2half2_rn(v.x, v.y);
    }
}

// ---------------- zero scores (for atomic-fused GEMM2 epilogue) ----------------
__global__ void k_zs() {
    int i = blockIdx.x * blockDim.x + threadIdx.x;
    if (i < NN) { g_ssrc[i] = 0.f; g_sdst[i] = 0.f; }
}

// ---------------- weight transpose + fp16 convert: out[n][k] = half(in[k][n]) ----------------
__global__ void k_transpose_h(const float* __restrict__ in, __half* __restrict__ out,
                              int K, int N) {
    __shared__ __half tile[32][34];
    int n0 = blockIdx.x * 32, k0 = blockIdx.y * 32;
    int tx = threadIdx.x, ty = threadIdx.y;   // 32 x 8
    #pragma unroll
    for (int i = 0; i < 4; i++) {
        int k = k0 + ty + i * 8;
        tile[ty + i * 8][tx] = __float2half_rn(in[(size_t)k * N + n0 + tx]);
    }
    __syncthreads();
    #pragma unroll
    for (int i = 0; i < 4; i++) {
        int n = n0 + ty + i * 8;
        out[(size_t)n * K + k0 + tx] = tile[tx][ty + i * 8];
    }
}

// ---------------- CSR build ----------------
__global__ void k_zerodeg() {
    int i = blockIdx.x * blockDim.x + threadIdx.x;
    if (i < NN) g_deg[i] = 0;
}
__global__ void k_deg(const int* __restrict__ ei) {
    int e = blockIdx.x * blockDim.x + threadIdx.x;
    if (e >= EE) return;
    int s, d; edge_sd(ei, e, s, d);
    atomicAdd(&g_deg[d], 1);
}
__global__ void k_scan() {   // single block, 1024 threads, chunk=10
    __shared__ int sh[1024];
    int tid = threadIdx.x;
    int base = tid * 10;
    int cnt[10]; int local = 0;
    #pragma unroll
    for (int i = 0; i < 10; i++) {
        int idx = base + i;
        int c = (idx < NN) ? g_deg[idx] : 0;
        cnt[i] = local; local += c;
    }
    sh[tid] = local;
    __syncthreads();
    for (int off = 1; off < 1024; off <<= 1) {
        int v = (tid >= off) ? sh[tid - off] : 0;
        __syncthreads();
        sh[tid] += v;
        __syncthreads();
    }
    int start = sh[tid] - local;
    #pragma unroll
    for (int i = 0; i < 10; i++) {
        int idx = base + i;
        if (idx < NN) { g_off[idx] = start + cnt[i]; g_cursor[idx] = 0; }
    }
    if (tid == 1023) g_off[NN] = sh[1023];
}
__global__ void k_fill(const int* __restrict__ ei) {
    int e = blockIdx.x * blockDim.x + threadIdx.x;
    if (e >= EE) return;
    int s, d; edge_sd(ei, e, s, d);
    int p = atomicAdd(&g_cursor[d], 1);
    g_csr[g_off[d] + p] = s;
}

// ---------------- attention-vector & node-score kernels ----------------
__global__ void k_v1(const float* __restrict__ W1, const float* __restrict__ as,
                     const float* __restrict__ ad) {
    int r = blockIdx.x;
    int tid = threadIdx.x;
    float ss = 0.f, sd = 0.f;
    const float* wrow = W1 + (size_t)r * F1;
    for (int j = tid; j < F1; j += 256) {
        float w = wrow[j];
        ss += w * as[j];
        sd += w * ad[j];
    }
    __shared__ float s1[256], s2[256];
    s1[tid] = ss; s2[tid] = sd;
    __syncthreads();
    for (int s = 128; s > 0; s >>= 1) {
        if (tid < s) { s1[tid] += s1[tid + s]; s2[tid] += s2[tid + s]; }
        __syncthreads();
    }
    if (tid == 0) { g_v1s[r] = s1[0]; g_v1d[r] = s2[0]; }
}

__global__ void k_scores(const float* __restrict__ X, const float* __restrict__ vs,
                         const float* __restrict__ vd, int F) {
    int node = blockIdx.x;
    int tid = threadIdx.x;      // 128
    const float* xr = X + (size_t)node * F;
    float ss = 0.f, sd = 0.f;
    for (int j = tid; j < F; j += 128) {
        float x = xr[j];
        ss += x * vs[j];
        sd += x * vd[j];
    }
    __shared__ float s1[128], s2[128];
    s1[tid] = ss; s2[tid] = sd;
    __syncthreads();
    for (int s = 64; s > 0; s >>= 1) {
        if (tid < s) { s1[tid] += s1[tid + s]; s2[tid] += s2[tid + s]; }
        __syncthreads();
    }
    if (tid == 0) { g_ssrc[node] = s1[0]; g_sdst[node] = s2[0]; }
}

// ---------------- per-node softmax -> per-edge alpha (warp per node) ----------------
__global__ void k_nd() {
    int w = (blockIdx.x * blockDim.x + threadIdx.x) >> 5;
    if (w >= NN) return;
    int lane = threadIdx.x & 31;
    int rs = g_off[w], re = g_off[w + 1];
    float sdv = g_sdst[w];
    float m = -1e30f;
    for (int j = rs + lane; j < re; j += 32)
        m = fmaxf(m, lrelu(g_ssrc[g_csr[j]] + sdv));
    #pragma unroll
    for (int o = 16; o > 0; o >>= 1) m = fmaxf(m, __shfl_xor_sync(0xffffffff, m, o));
    float den = 0.f;
    for (int j = rs + lane; j < re; j += 32)
        den += __expf(lrelu(g_ssrc[g_csr[j]] + sdv) - m);
    #pragma unroll
    for (int o = 16; o > 0; o >>= 1) den += __shfl_xor_sync(0xffffffff, den, o);
    float inv = 1.0f / den;
    for (int j = rs + lane; j < re; j += 32)
        g_ew[j] = __expf(lrelu(g_ssrc[g_csr[j]] + sdv) - m) * inv;
}

// ---------------- gather aggregation (weights precomputed, no atomics) ----------------
__global__ void k_gat1() {
    int n = blockIdx.x, tid = threadIdx.x;   // 128 threads, 4 halves each
    int rs = g_off[n], re = g_off[n + 1];
    float4 acc = make_float4(0.f, 0.f, 0.f, 0.f);
    int j = rs;
    for (; j + 2 <= re; j += 2) {
        int s0 = g_csr[j], s1 = g_csr[j + 1];
        float w0 = g_ew[j], w1 = g_ew[j + 1];
        uint2 u0 = ((const uint2*)(g_xh + (size_t)s0 * F0))[tid];
        uint2 u1 = ((const uint2*)(g_xh + (size_t)s1 * F0))[tid];
        float2 a0 = __half22float2(*(__half2*)&u0.x);
        float2 a1 = __half22float2(*(__half2*)&u0.y);
        float2 b0 = __half22float2(*(__half2*)&u1.x);
        float2 b1 = __half22float2(*(__half2*)&u1.y);
        acc.x += w0 * a0.x; acc.y += w0 * a0.y; acc.z += w0 * a1.x; acc.w += w0 * a1.y;
        acc.x += w1 * b0.x; acc.y += w1 * b0.y; acc.z += w1 * b1.x; acc.w += w1 * b1.y;
    }
    if (j < re) {
        int s0 = g_csr[j];
        float w0 = g_ew[j];
        uint2 u0 = ((const uint2*)(g_xh + (size_t)s0 * F0))[tid];
        float2 a0 = __half22float2(*(__half2*)&u0.x);
        float2 a1 = __half22float2(*(__half2*)&u0.y);
        acc.x += w0 * a0.x; acc.y += w0 * a0.y; acc.z += w0 * a1.x; acc.w += w0 * a1.y;
    }
    __half2 h0 = __floats2half2_rn(acc.x, acc.y);
    __half2 h1v = __floats2half2_rn(acc.z, acc.w);
    __half2* o = (__half2*)(g_agg1h + (size_t)n * F0);
    o[tid * 2 + 0] = h0;
    o[tid * 2 + 1] = h1v;
}

__global__ void k_gat2(const float* __restrict__ b2) {
    int n = blockIdx.x, tid = threadIdx.x;   // 256 threads, 4 halves each
    int rs = g_off[n], re = g_off[n + 1];
    float4 acc = make_float4(0.f, 0.f, 0.f, 0.f);
    int j = rs;
    for (; j + 2 <= re; j += 2) {
        int s0 = g_csr[j], s1 = g_csr[j + 1];
        float w0 = g_ew[j], w1 = g_ew[j + 1];
        uint2 u0 = ((const uint2*)(g_h2h + (size_t)s0 * F2))[tid];
        uint2 u1 = ((const uint2*)(g_h2h + (size_t)s1 * F2))[tid];
        float2 a0 = __half22float2(*(__half2*)&u0.x);
        float2 a1 = __half22float2(*(__half2*)&u0.y);
        float2 b0v = __half22float2(*(__half2*)&u1.x);
        float2 b1v = __half22float2(*(__half2*)&u1.y);
        acc.x += w0 * a0.x; acc.y += w0 * a0.y; acc.z += w0 * a1.x; acc.w += w0 * a1.y;
        acc.x += w1 * b0v.x; acc.y += w1 * b0v.y; acc.z += w1 * b1v.x; acc.w += w1 * b1v.y;
    }
    if (j < re) {
        int s0 = g_csr[j];
        float w0 = g_ew[j];
        uint2 u0 = ((const uint2*)(g_h2h + (size_t)s0 * F2))[tid];
        float2 a0 = __half22float2(*(__half2*)&u0.x);
        float2 a1 = __half22float2(*(__half2*)&u0.y);
        acc.x += w0 * a0.x; acc.y += w0 * a0.y; acc.z += w0 * a1.x; acc.w += w0 * a1.y;
    }
    float4 bv = ((const float4*)b2)[tid];
    acc.x = fmaxf(acc.x + bv.x, 0.f);
    acc.y = fmaxf(acc.y + bv.y, 0.f);
    acc.z = fmaxf(acc.z + bv.z, 0.f);
    acc.w = fmaxf(acc.w + bv.w, 0.f);
    ((float4*)(g_agg2 + (size_t)n * F2))[tid] = acc;
}

// ---------------- layer 3: warp-per-node GEMM + fused scores ----------------
__global__ void k_gemm3(const float* __restrict__ W3, const float* __restrict__ as3,
                        const float* __restrict__ ad3) {
    int w = (blockIdx.x * blockDim.x + threadIdx.x) >> 5;
    if (w >= NN) return;
    int lane = threadIdx.x & 31;
    const float* a = g_agg2 + (size_t)w * F2;
    float acc[F3];
    #pragma unroll
    for (int j = 0; j < F3; j++) acc[j] = 0.f;
    for (int k = lane; k < F2; k += 32) {
        float av = a[k];
        #pragma unroll
        for (int j = 0; j < F3; j++) acc[j] += av * W3[k * F3 + j];
    }
    float ss = 0.f, sd = 0.f;
    #pragma unroll
    for (int j = 0; j < F3; j++) {
        float s = acc[j];
        #pragma unroll
        for (int o = 16; o > 0; o >>= 1) s += __shfl_xor_sync(0xffffffff, s, o);
        if (lane == 0) g_h3[w * F3 + j] = s;
        ss += s * as3[j];
        sd += s * ad3[j];
    }
    if (lane == 0) { g_ssrc[w] = ss; g_sdst[w] = sd; }
}

__global__ void k_gat3f(const float* __restrict__ b3, float* __restrict__ out) {
    int wg = (blockIdx.x * blockDim.x + threadIdx.x) >> 5;
    if (wg >= NN) return;
    int lane = threadIdx.x & 31;
    int rs = g_off[wg], re = g_off[wg + 1];
    float acc = 0.f;
    for (int j = rs; j < re; j++) {
        int s = g_csr[j];
        float w = g_ew[j];
        if (lane < F3) acc += w * g_h3[s * F3 + lane];
    }
    float z = (lane < F3) ? acc + b3[lane] : -1e30f;
    float mz = z;
    #pragma unroll
    for (int o = 16; o > 0; o >>= 1) mz = fmaxf(mz, __shfl_xor_sync(0xffffffff, mz, o));
    float e = (lane < F3) ? expf(z - mz) : 0.f;
    #pragma unroll
    for (int o = 16; o > 0; o >>= 1) e += __shfl_xor_sync(0xffffffff, e, o);
    float l = mz + logf(e);
    if (lane < F3) out[wg * F3 + lane] = z - l;
}

// ---------------- fp16 mma.sync GEMM, ldmatrix + 3-stage cp.async (templated) ----------------
// WMW warps in M, WNW warps in N, NU n8-tiles per warp. BM=WMW*32, BN=WNW*NU*8.
// Optional fused scores: atomicAdd partial dot(avs/avd) per output row (pre-bias acc).
#define SH_STR 72
#define NSTAGE 3

template<int WMW, int WNW, int NU>
__global__ void __launch_bounds__(WMW * WNW * 32, 1)
tc_gemm(const __half* __restrict__ A, const __half* __restrict__ Bt, void* __restrict__ Cv,
        int M, int Nc, int K, const float* __restrict__ bias, int doRelu, int outHalf,
        const float* __restrict__ avs, const float* __restrict__ avd) {
    constexpr int THREADS = WMW * WNW * 32;
    constexpr int BM = WMW * 32;
    constexpr int WNC = NU * 8;
    constexpr int BN = WNW * WNC;
    constexpr int STA = BM * SH_STR * 2;
    constexpr int STB = BN * SH_STR * 2;
    constexpr int STBY = STA + STB;
    constexpr int ACH = BM * 8;
    constexpr int BCH = BN * 8;

    extern __shared__ __half smh[];
    uint32_t smu = smem_u32(smh);
    int tid = threadIdx.x;
    int lane = tid & 31, wid = tid >> 5;
    int warp_m = wid % WMW, warp_n = wid / WMW;
    int g = lane >> 2, c = lane & 3;
    int lr = lane & 7, lm = lane >> 3;
    int row0 = blockIdx.y * BM, col0 = blockIdx.x * BN;

    uint32_t a_loff = ((uint32_t)(warp_m * 32 + lr + (lm & 1) * 8) * SH_STR
                       + ((lm >> 1) & 1) * 8) * 2;
    uint32_t b_loff = (uint32_t)STA
                      + ((uint32_t)(warp_n * WNC + lr + ((lm >> 1) & 1) * 8) * SH_STR
                         + (lm & 1) * 8) * 2;

    float acc[2][NU][4];
    #pragma unroll
    for (int t = 0; t < 2; t++)
        #pragma unroll
        for (int u = 0; u < NU; u++)
            #pragma unroll
            for (int j = 0; j < 4; j++) acc[t][u][j] = 0.f;

    const int KT = K >> 6;

    auto fill = [&](int kt, int stage) {
        uint32_t sa_u = smu + stage * STBY;
        uint32_t sb_u = sa_u + STA;
        #pragma unroll
        for (int i = 0; i < (ACH + THREADS - 1) / THREADS; i++) {
            int idx = i * THREADS + tid;
            if ((ACH % THREADS) == 0 || idx < ACH) {
                int m = idx >> 3, k8 = idx & 7;
                int gr = row0 + m;
                int ok = gr < M;
                const __half* src = A + (size_t)(ok ? gr : row0) * K + kt * 64 + k8 * 8;
                cpa16(sa_u + (uint32_t)(m * SH_STR + k8 * 8) * 2, src, ok ? 16 : 0);
            }
        }
        #pragma unroll
        for (int i = 0; i < (BCH + THREADS - 1) / THREADS; i++) {
            int idx = i * THREADS + tid;
            if ((BCH % THREADS) == 0 || idx < BCH) {
                int n = idx >> 3, k8 = idx & 7;
                const __half* src = Bt + (size_t)(col0 + n) * K + kt * 64 + k8 * 8;
                cpa16(sb_u + (uint32_t)(n * SH_STR + k8 * 8) * 2, src, 16);
            }
        }
        asm volatile("cp.async.commit_group;" ::: "memory");
    };

    fill(0, 0);
    if (KT > 1) fill(1, 1);

    for (int kt = 0; kt < KT; kt++) {
        int buf = kt % NSTAGE;
        if (kt + 2 < KT) {
            fill(kt + 2, (kt + 2) % NSTAGE);
            asm volatile("cp.async.wait_group 2;" ::: "memory");
        } else if (kt + 1 < KT) {
            asm volatile("cp.async.wait_group 1;" ::: "memory");
        } else {
            asm volatile("cp.async.wait_group 0;" ::: "memory");
        }
        __syncthreads();
        uint32_t st = smu + buf * STBY;
        #pragma unroll
        for (int ks = 0; ks < 4; ks++) {
            uint32_t af[2][4];
            #pragma unroll
            for (int t = 0; t < 2; t++)
                ldm4(af[t], st + a_loff + (uint32_t)(t * 16 * SH_STR * 2) + ks * 32);
            uint32_t bf[NU][2];
            #pragma unroll
            for (int p = 0; p < NU / 2; p++) {
                uint32_t r4[4];
                ldm4(r4, st + b_loff + (uint32_t)(p * 16 * SH_STR * 2) + ks * 32);
                bf[p * 2][0] = r4[0];     bf[p * 2][1] = r4[1];
                bf[p * 2 + 1][0] = r4[2]; bf[p * 2 + 1][1] = r4[3];
            }
            #pragma unroll
            for (int t = 0; t < 2; t++)
                #pragma unroll
                for (int u = 0; u < NU; u++)
                    mma16(acc[t][u], af[t], bf[u]);
        }
        __syncthreads();
    }

    // epilogue: store (+bias/relu), optional fused scores from raw acc
    #pragma unroll
    for (int t = 0; t < 2; t++) {
        int r0 = row0 + warp_m * 32 + t * 16 + g;
        #pragma unroll
        for (int u = 0; u < NU; u++) {
            int cc = col0 + warp_n * WNC + u * 8 + 2 * c;
            float2 v0 = make_float2(acc[t][u][0], acc[t][u][1]);
            float2 v1 = make_float2(acc[t][u][2], acc[t][u][3]);
            if (bias) {
                float b0v = bias[cc], b1v = bias[cc + 1];
                v0.x += b0v; v0.y += b1v;
                v1.x += b0v; v1.y += b1v;
            }
            if (doRelu) {
                v0.x = fmaxf(v0.x, 0.f); v0.y = fmaxf(v0.y, 0.f);
                v1.x = fmaxf(v1.x, 0.f); v1.y = fmaxf(v1.y, 0.f);
            }
            if (outHalf) {
                __half* C = (__half*)Cv;
                if (r0 < M)
                    *(__half2*)(C + (size_t)r0 * Nc + cc) = __floats2half2_rn(v0.x, v0.y);
                if (r0 + 8 < M)
                    *(__half2*)(C + (size_t)(r0 + 8) * Nc + cc) = __floats2half2_rn(v1.x, v1.y);
            } else {
                float* C = (float*)Cv;
                if (r0 < M)     *(float2*)(C + (size_t)r0 * Nc + cc) = v0;
                if (r0 + 8 < M) *(float2*)(C + (size_t)(r0 + 8) * Nc + cc) = v1;
            }
        }
        if (avs) {
            float ss0 = 0.f, sd0 = 0.f, ss1 = 0.f, sd1 = 0.f;
            #pragma unroll
            for (int u = 0; u < NU; u++) {
                int cc = col0 + warp_n * WNC + u * 8 + 2 * c;
                float a0 = avs[cc], a1 = avs[cc + 1];
                float d0 = avd[cc], d1 = avd[cc + 1];
                ss0 += acc[t][u][0] * a0 + acc[t][u][1] * a1;
                sd0 += acc[t][u][0] * d0 + acc[t][u][1] * d1;
                ss1 += acc[t][u][2] * a0 + acc[t][u][3] * a1;
                sd1 += acc[t][u][2] * d0 + acc[t][u][3] * d1;
            }
            #pragma unroll
            for (int o = 1; o < 4; o <<= 1) {
                ss0 += __shfl_xor_sync(0xffffffff, ss0, o);
                sd0 += __shfl_xor_sync(0xffffffff, sd0, o);
                ss1 += __shfl_xor_sync(0xffffffff, ss1, o);
                sd1 += __shfl_xor_sync(0xffffffff, sd1, o);
            }
            if (c == 0) {
                if (r0 < M)     { atomicAdd(&g_ssrc[r0], ss0); atomicAdd(&g_sdst[r0], sd0); }
                if (r0 + 8 < M) { atomicAdd(&g_ssrc[r0 + 8], ss1); atomicAdd(&g_sdst[r0 + 8], sd1); }
            }
        }
    }
}

// GEMM1: 4x4 warps, NU=8 -> BM=128, BN=256, 512 thr.
// GEMM2: 5x4 warps, NU=4 -> BM=160, BN=128, 640 thr.
#define SMB_G1 (NSTAGE * (128 * SH_STR * 2 + 256 * SH_STR * 2))
#define SMB_G2 (NSTAGE * (160 * SH_STR * 2 + 128 * SH_STR * 2))

// ---------------- launch ----------------
extern "C" void kernel_launch(void* const* d_in, const int* in_sizes, int n_in,
                              void* d_out, int out_size) {
    const float* x   = (const float*)d_in[0];
    const int*   ei  = (const int*)d_in[1];
    const float* W1  = (const float*)d_in[2];
    const float* as1 = (const float*)d_in[3];
    const float* ad1 = (const float*)d_in[4];
    const float* b1  = (const float*)d_in[5];
    const float* W2  = (const float*)d_in[6];
    const float* as2 = (const float*)d_in[7];
    const float* ad2 = (const float*)d_in[8];
    const float* b2  = (const float*)d_in[9];
    const float* W3  = (const float*)d_in[10];
    const float* as3 = (const float*)d_in[11];
    const float* ad3 = (const float*)d_in[12];
    const float* b3  = (const float*)d_in[13];
    float* out = (float*)d_out;

    void *p_agg1h, *p_h1h, *p_h2h, *p_v1s, *p_v1d, *p_w1t, *p_w2t;
    cudaGetSymbolAddress(&p_agg1h, g_agg1h);
    cudaGetSymbolAddress(&p_h1h, g_h1h);
    cudaGetSymbolAddress(&p_h2h, g_h2h);
    cudaGetSymbolAddress(&p_v1s, g_v1s);
    cudaGetSymbolAddress(&p_v1d, g_v1d);
    cudaGetSymbolAddress(&p_w1t, g_w1t);
    cudaGetSymbolAddress(&p_w2t, g_w2t);

    cudaFuncSetAttribute(tc_gemm<4, 4, 8>, cudaFuncAttributeMaxDynamicSharedMemorySize, SMB_G1);
    cudaFuncSetAttribute(tc_gemm<5, 4, 4>, cudaFuncAttributeMaxDynamicSharedMemorySize, SMB_G2);

    const int EB = (EE + 255) / 256;
    const int NWB = (NN * 32 + 255) / 256;   // warp-per-node grids

    // ---- independent prep: x->half, weight transposes ----
    k_xh<<<2048, 256>>>(x);
    k_transpose_h<<<dim3(F1 / 32, F0 / 32), dim3(32, 8)>>>(W1, (__half*)p_w1t, F0, F1);
    k_transpose_h<<<dim3(F2 / 32, F1 / 32), dim3(32, 8)>>>(W2, (__half*)p_w2t, F1, F2);

    // ---- CSR build (reused by all 3 layers) ----
    k_zerodeg<<<(NN + 255) / 256, 256>>>();
    k_deg<<<EB, 256>>>(ei);
    k_scan<<<1, 1024>>>();
    k_fill<<<EB, 256>>>(ei);

    // ---- Layer 1: scores on x, alpha, gather (half src), GEMM ----
    k_v1<<<F0, 256>>>(W1, as1, ad1);
    k_scores<<<NN, 128>>>(x, (const float*)p_v1s, (const float*)p_v1d, F0);
    k_nd<<<NWB, 256>>>();
    k_gat1<<<NN, 128>>>();
    {
        dim3 grd(F1 / 256, (NN + 127) / 128);
        tc_gemm<4, 4, 8><<<grd, 512, SMB_G1>>>((const __half*)p_agg1h, (const __half*)p_w1t,
                                               p_h1h, NN, F1, F0, b1, 1, 1, nullptr, nullptr);
    }

    // ---- Layer 2: zero scores, GEMM (fused scores via atomics), alpha, gather ----
    k_zs<<<(NN + 255) / 256, 256>>>();
    {
        dim3 grd(F2 / 128, (NN + 159) / 160);
        tc_gemm<5, 4, 4><<<grd, 640, SMB_G2>>>((const __half*)p_h1h, (const __half*)p_w2t,
                                               p_h2h, NN, F2, F1, nullptr, 0, 1, as2, ad2);
    }
    k_nd<<<NWB, 256>>>();
    k_gat2<<<NN, 256>>>(b2);

    // ---- Layer 3: warp-per-node GEMM (+fused scores), alpha, gather+log_softmax ----
    k_gemm3<<<NWB, 256>>>(W3, as3, ad3);
    k_nd<<<NWB, 256>>>();
    k_gat3f<<<NWB, 256>>>(b3, out);
}